// round 12
// baseline (speedup 1.0000x reference)
#include <cuda_runtime.h>
#include <cuda_fp16.h>
#include <math.h>
#include <stdint.h>

#define NQ 1024
#define NS 256
#define E  256
#define H1 256
#define H2 128
#define H3 64
#define TM 128          // query rows per CTA (x2 support cols)

// ---------------- warp-MMA helpers (plain sm_80+ PTX) -----------------------
__device__ __forceinline__ uint32_t smem_to_u32(const void* p) {
    uint32_t a;
    asm("{ .reg .u64 t; cvta.to.shared.u64 t, %1; cvt.u32.u64 %0, t; }" : "=r"(a) : "l"(p));
    return a;
}
__device__ __forceinline__ void ldsm4(uint32_t* r, uint32_t addr) {
    asm volatile("ldmatrix.sync.aligned.m8n8.x4.shared.b16 {%0,%1,%2,%3}, [%4];"
                 : "=r"(r[0]), "=r"(r[1]), "=r"(r[2]), "=r"(r[3]) : "r"(addr));
}
__device__ __forceinline__ void mma_f16(float* d, const uint32_t* a, const uint32_t* b) {
    asm volatile("mma.sync.aligned.m16n8k16.row.col.f32.f16.f16.f32 "
                 "{%0,%1,%2,%3}, {%4,%5,%6,%7}, {%8,%9}, {%0,%1,%2,%3};"
                 : "+f"(d[0]), "+f"(d[1]), "+f"(d[2]), "+f"(d[3])
                 : "r"(a[0]), "r"(a[1]), "r"(a[2]), "r"(a[3]), "r"(b[0]), "r"(b[1]));
}
__device__ __forceinline__ void cp_async16(uint32_t dst_smem, const void* src) {
    asm volatile("cp.async.cg.shared.global [%0], [%1], 16;"
                 :: "r"(dst_smem), "l"(src));
}
#define CP_ASYNC_COMMIT() asm volatile("cp.async.commit_group;" ::: "memory")
#define CP_ASYNC_WAIT0()  asm volatile("cp.async.wait_group 0;" ::: "memory")

__device__ __forceinline__ void split_f16(float x, __half& hi, __half& lo) {
    hi = __float2half_rn(x);
    lo = __float2half_rn(x - __half2float(hi));
}
__device__ __forceinline__ uint32_t pack2h(__half a, __half b) {
    __half2 t; t.x = a; t.y = b;
    return *reinterpret_cast<uint32_t*>(&t);
}
__device__ __forceinline__ uint32_t hadd2_relu(uint32_t a, uint32_t b) {
    __half2 r = __hmax2(__hadd2(*reinterpret_cast<__half2*>(&a),
                                *reinterpret_cast<__half2*>(&b)),
                        __half2(__half(0.0f), __half(0.0f)));
    return *reinterpret_cast<uint32_t*>(&r);
}
__device__ __forceinline__ float frelu(float x) { return fmaxf(x, 0.0f); }

// ---------------- global scratch (static) -----------------------------------
__device__ uint4  g_QpF[16 * 64 * 32];        // [K16][M16][lane] fp16 A-fragments
__device__ float  g_Sp [NS * H1];             // [s][k] (+b1)
__device__ __half g_W1TB_hi[163840];          // [(half*8+c)*256+n]*40+kk (kk<32)
__device__ __half g_W1TB_lo[163840];
__device__ __half g_W2TB[128 * 264];          // [n][264k] fp16, k<256 data
__device__ __half g_W3TB[8704];               // [n*136+k] fp16

// ---------------- main-kernel smem layout (bytes) ----------------------------
#define SM_W2   0         // whole W2^T [128n][264k] fp16 = 67584
#define SM_W3   0         // phase B: W3^T [64n][136k] = 17408 (aliases SM_W2)
#define SM_H2   67584     // h2 fp16 x2 s: 2 x 34816 = 69632 (ends 137216)
#define H2_S    34816
#define SM_SP16 137216    // 2 x 256 fp16 = 1024
#define SM_B2S  138240    // 128 f32
#define SM_B3S  138752    // 64 f32
#define SM_W4S  139008    // 64 f32
#define SM_RED  139264    // 2 x 1024 = 2048
#define SMEM_TOTAL 141312

// ---------------- precompute-kernel smem layout ------------------------------
#define PSM_A  0          // feat fp16 [128m][264k] = 67584
#define PSM_B  67584      // W1 stage: 2 x (hi 10240 + lo 10240) = 40960
#define PB_STRIDE 20480
#define PRE_SMEM_TOTAL 108544

// ---------------------------------------------------------------------------
// W1 prep, coalesced: read W1 row-major (lane = n), scatter transposed
// hi/lo writes. Pad cols kk=32..39 are never read by ldsm (kcol<=24+8),
// so no zero-fill needed.
// ---------------------------------------------------------------------------
__global__ void prep_w1_kernel(const float* __restrict__ W1)
{
    const int t = blockIdx.x * blockDim.x + threadIdx.x;   // 512*256 = 131072
    const int row = t >> 8;            // 0..511 (k index into W1)
    const int n   = t & 255;
    const int hf  = row >> 8;
    const int c   = (row >> 5) & 7;
    const int kk  = row & 31;
    const float w = W1[row * H1 + n];
    __half hi, lo; split_f16(w, hi, lo);
    const int idx = ((hf * 8 + c) * 256 + n) * 40 + kk;
    g_W1TB_hi[idx] = hi;
    g_W1TB_lo[idx] = lo;
}

// ---------------------------------------------------------------------------
// Precompute via mma (f32 acc, W1 hi+lo): Qp -> g_QpF fragments; Sp -> g_Sp.
// mb 0..9: GEMM CTAs. mb 10..14: W2/W3 fp16 conversion (runs concurrently).
// ---------------------------------------------------------------------------
__global__ void __launch_bounds__(256)
precompute_mma_kernel(const float* __restrict__ qf,
                      const float* __restrict__ sf,
                      const float* __restrict__ b1,
                      const float* __restrict__ W2,
                      const float* __restrict__ W3)
{
    const int mb = blockIdx.x;         // 0..14
    const int nb = blockIdx.y;         // 0..1

    if (mb >= 10) {
        const int cid = (mb - 10) * 2 + nb;     // 0..9
        for (int e = cid * 256 + threadIdx.x; e < 33792 + 8704; e += 2560) {
            if (e < 33792) {
                const int n = e / 264, k = e % 264;
                const float w = (k < 256) ? W2[k * H2 + n] : 0.0f;
                g_W2TB[e] = __float2half_rn(w);
            } else {
                const int t = e - 33792;
                const int n = t / 136, k = t % 136;
                const float w = (k < 128) ? W3[k * H3 + n] : 0.0f;
                g_W3TB[t] = __float2half_rn(w);
            }
        }
        return;
    }

    extern __shared__ char smem[];
    const uint32_t sb = smem_to_u32(smem);
    const int tid  = threadIdx.x;
    const int lane = tid & 31;
    const int wid  = tid >> 5;
    const int wm   = wid & 3;
    const int wn   = wid >> 2;
    const bool isQ = (mb < 8);
    const float* feat = isQ ? (qf + mb * 128 * E) : (sf + (mb - 8) * 128 * E);
    const int hf = isQ ? 0 : 1;

    {
        const int row = tid >> 1, hv = tid & 1;
        const float4* src = reinterpret_cast<const float4*>(feat + row * E);
        uint32_t* dst = reinterpret_cast<uint32_t*>(smem + PSM_A);
        #pragma unroll 8
        for (int j = 0; j < 32; ++j) {
            const float4 v = src[hv * 32 + j];
            const int u = row * 132 + (hv * 32 + j) * 2;
            dst[u]     = pack2h(__float2half_rn(v.x), __float2half_rn(v.y));
            dst[u + 1] = pack2h(__float2half_rn(v.z), __float2half_rn(v.w));
        }
    }
    {
        const char* srcH = (const char*)&g_W1TB_hi[((hf * 8 + 0) * 256 + nb * 128) * 40];
        const char* srcL = (const char*)&g_W1TB_lo[((hf * 8 + 0) * 256 + nb * 128) * 40];
        const uint32_t dstH = sb + PSM_B;
        #pragma unroll
        for (int i = 0; i < 3; ++i) {
            const int t = tid + 256 * i;
            if (t < 640) {
                cp_async16(dstH + t * 16, srcH + t * 16);
                cp_async16(dstH + 10240 + t * 16, srcL + t * 16);
            }
        }
        CP_ASYNC_COMMIT();
    }
    __syncthreads();

    float acc[2][8][4];
    #pragma unroll
    for (int a = 0; a < 2; a++)
        #pragma unroll
        for (int b = 0; b < 8; b++)
            #pragma unroll
            for (int c = 0; c < 4; c++) acc[a][b][c] = 0.0f;

    for (int c = 0; c < 8; ++c) {
        const int st = c & 1;
        CP_ASYNC_WAIT0();
        __syncthreads();
        if (c < 7) {
            const int base = ((hf * 8 + c + 1) * 256 + nb * 128) * 40;
            const char* srcH = (const char*)&g_W1TB_hi[base];
            const char* srcL = (const char*)&g_W1TB_lo[base];
            const uint32_t dstH = sb + PSM_B + (st ^ 1) * PB_STRIDE;
            #pragma unroll
            for (int i = 0; i < 3; ++i) {
                const int t = tid + 256 * i;
                if (t < 640) {
                    cp_async16(dstH + t * 16, srcH + t * 16);
                    cp_async16(dstH + 10240 + t * 16, srcL + t * 16);
                }
            }
            CP_ASYNC_COMMIT();
        }
        const uint32_t bufH = sb + PSM_B + st * PB_STRIDE;
        #pragma unroll
        for (int ks = 0; ks < 2; ++ks) {
            uint32_t afr[2][4];
            #pragma unroll
            for (int tm = 0; tm < 2; ++tm) {
                const int mrow = wm * 32 + tm * 16 + (lane & 7) + 8 * ((lane >> 3) & 1);
                const int kcol = c * 32 + ks * 16 + 8 * (lane >> 4);
                ldsm4(afr[tm], sb + PSM_A + mrow * 528 + kcol * 2);
            }
            #pragma unroll
            for (int tp = 0; tp < 4; ++tp) {
                uint32_t bh[4], bl[4];
                const int nrow = wn * 64 + tp * 16 + (lane & 7) + 8 * (lane >> 4);
                const int kcol = ks * 16 + 8 * ((lane >> 3) & 1);
                const uint32_t baddr = bufH + nrow * 80 + kcol * 2;
                ldsm4(bh, baddr);
                ldsm4(bl, baddr + 10240);
                #pragma unroll
                for (int tm = 0; tm < 2; ++tm) {
                    mma_f16(acc[tm][2*tp    ], afr[tm], &bh[0]);
                    mma_f16(acc[tm][2*tp    ], afr[tm], &bl[0]);
                    mma_f16(acc[tm][2*tp + 1], afr[tm], &bh[2]);
                    mma_f16(acc[tm][2*tp + 1], afr[tm], &bl[2]);
                }
            }
        }
    }

    if (isQ) {
        #pragma unroll
        for (int tm = 0; tm < 2; ++tm)
            #pragma unroll
            for (int tnp = 0; tnp < 4; ++tnp) {
                const int K16 = nb * 8 + wn * 4 + tnp;
                const int M16 = mb * 8 + wm * 2 + tm;
                uint4 v;
                v.x = pack2h(__float2half_rn(acc[tm][2*tnp][0]),
                             __float2half_rn(acc[tm][2*tnp][1]));
                v.y = pack2h(__float2half_rn(acc[tm][2*tnp][2]),
                             __float2half_rn(acc[tm][2*tnp][3]));
                v.z = pack2h(__float2half_rn(acc[tm][2*tnp+1][0]),
                             __float2half_rn(acc[tm][2*tnp+1][1]));
                v.w = pack2h(__float2half_rn(acc[tm][2*tnp+1][2]),
                             __float2half_rn(acc[tm][2*tnp+1][3]));
                g_QpF[(K16 * 64 + M16) * 32 + lane] = v;
            }
    } else {
        const int s0 = (mb - 8) * 128;
        #pragma unroll
        for (int tm = 0; tm < 2; ++tm)
            #pragma unroll
            for (int tn = 0; tn < 8; ++tn) {
                const int n = nb * 128 + wn * 64 + tn * 8 + (lane & 3) * 2;
                const float bb0 = b1[n], bb1 = b1[n + 1];
                #pragma unroll
                for (int rr = 0; rr < 2; ++rr) {
                    const int m = wm * 32 + tm * 16 + rr * 8 + (lane >> 2);
                    g_Sp[(s0 + m) * H1 + n]     = acc[tm][tn][2*rr]     + bb0;
                    g_Sp[(s0 + m) * H1 + n + 1] = acc[tm][tn][2*rr + 1] + bb1;
                }
            }
    }
}

// ---------------------------------------------------------------------------
// Fused MLP, dual support columns: one CTA = 128 q x 2 s. W2/Qp loaded once
// for both columns (halves L2 traffic); B ldsm reused across s (4 mma/ldsm).
// ---------------------------------------------------------------------------
__global__ void __launch_bounds__(256, 1)
relation_mma_kernel(const float* __restrict__ b2,
                    const float* __restrict__ b3,
                    const float* __restrict__ W4,
                    const float* __restrict__ b4,
                    float* __restrict__ out)
{
    extern __shared__ char smem[];
    const uint32_t sb = smem_to_u32(smem);
    const int tid  = threadIdx.x;
    const int lane = tid & 31;
    const int wid  = tid >> 5;
    const int wm   = wid & 3;
    const int wn   = wid >> 2;
    const int s0   = blockIdx.x * 2;       // 2 support columns per CTA
    const int q0   = blockIdx.y * TM;
    const int M16b = blockIdx.y * 8 + wm * 2;

    float* b2s = (float*)(smem + SM_B2S);
    float* b3s = (float*)(smem + SM_B3S);
    float* W4s = (float*)(smem + SM_W4S);
    float* red = (float*)(smem + SM_RED);
    __half* sp16 = (__half*)(smem + SM_SP16);

    sp16[tid]       = __float2half_rn(g_Sp[s0 * H1 + tid]);
    sp16[256 + tid] = __float2half_rn(g_Sp[(s0 + 1) * H1 + tid]);
    if (tid < H2) b2s[tid] = b2[tid];
    if (tid < H3) { b3s[tid] = b3[tid]; W4s[tid] = W4[tid]; }

    // ---- prologue: cp.async the WHOLE W2 (67584 B = 4224 x 16B) ----
    {
        const char* src = (const char*)g_W2TB;
        #pragma unroll
        for (int i = 0; i < 17; ++i) {
            const int t = tid + 256 * i;
            if (t < 4224) cp_async16(sb + SM_W2 + t * 16, src + t * 16);
        }
        CP_ASYNC_COMMIT();
    }
    uint4 aq[2][2];
    #pragma unroll
    for (int tm = 0; tm < 2; ++tm)
        #pragma unroll
        for (int ks = 0; ks < 2; ++ks)
            aq[tm][ks] = g_QpF[(ks * 64 + M16b + tm) * 32 + lane];

    float acc[2][2][8][4];   // [s][tm][tn][quad] = 128 f32
    #pragma unroll
    for (int s = 0; s < 2; s++)
        #pragma unroll
        for (int a = 0; a < 2; a++)
            #pragma unroll
            for (int b = 0; b < 8; b++)
                #pragma unroll
                for (int c = 0; c < 4; c++) acc[s][a][b][c] = 0.0f;

    CP_ASYNC_WAIT0();
    __syncthreads();   // W2 + sp16 + biases visible; only barrier before loop

    // ============ layer2 mainloop: 8 chunks of k=32, barrier-free ===========
    #pragma unroll
    for (int c = 0; c < 8; ++c) {
        #pragma unroll
        for (int ks = 0; ks < 2; ++ks) {
            uint32_t af[2][2][4];   // [s][tm][quad]
            const uint32_t off = c * 64 + ks * 32 + (lane & 3) * 4;
            #pragma unroll
            for (int s = 0; s < 2; ++s) {
                const uint32_t spA = *(const uint32_t*)(smem + SM_SP16 + s * 512 + off);
                const uint32_t spB = *(const uint32_t*)(smem + SM_SP16 + s * 512 + off + 16);
                #pragma unroll
                for (int tm = 0; tm < 2; ++tm) {
                    af[s][tm][0] = hadd2_relu(aq[tm][ks].x, spA);
                    af[s][tm][1] = hadd2_relu(aq[tm][ks].y, spA);
                    af[s][tm][2] = hadd2_relu(aq[tm][ks].z, spB);
                    af[s][tm][3] = hadd2_relu(aq[tm][ks].w, spB);
                }
            }
            if (c < 7) {   // aq[.][ks] consumed; prefetch next chunk's
                #pragma unroll
                for (int tm = 0; tm < 2; ++tm)
                    aq[tm][ks] = g_QpF[(((c + 1) * 2 + ks) * 64 + M16b + tm) * 32 + lane];
            }
            #pragma unroll
            for (int tp = 0; tp < 4; ++tp) {
                uint32_t bh[4];
                const int nrow = wn * 64 + tp * 16 + (lane & 7) + 8 * (lane >> 4);
                const int kcol = c * 32 + ks * 16 + 8 * ((lane >> 3) & 1);
                ldsm4(bh, sb + SM_W2 + nrow * 528 + kcol * 2);
                #pragma unroll
                for (int s = 0; s < 2; ++s)
                    #pragma unroll
                    for (int tm = 0; tm < 2; ++tm) {
                        mma_f16(acc[s][tm][2*tp    ], af[s][tm], &bh[0]);
                        mma_f16(acc[s][tm][2*tp + 1], af[s][tm], &bh[2]);
                    }
            }
        }
    }
    __syncthreads();   // all W2 reads done CTA-wide; W2 region reusable

    // stage W3^T into W2's region via cp.async (overlaps epilogue below)
    {
        const char* srcH = (const char*)g_W3TB;
        #pragma unroll
        for (int i = 0; i < 5; ++i) {
            const int t = tid + 256 * i;
            if (t < 1088) cp_async16(sb + SM_W3 + t * 16, srcH + t * 16);
        }
        CP_ASYNC_COMMIT();
    }
    // layer2 epilogue: bias+relu -> fp16 -> h2[s][m][k]
    #pragma unroll
    for (int s = 0; s < 2; ++s) {
        uint32_t* hh = reinterpret_cast<uint32_t*>(smem + SM_H2 + s * H2_S);
        #pragma unroll
        for (int tm = 0; tm < 2; ++tm) {
            #pragma unroll
            for (int tn = 0; tn < 8; ++tn) {
                const int n = wn * 64 + tn * 8 + (lane & 3) * 2;
                const int m = wm * 32 + tm * 16 + (lane >> 2);
                const float bn0 = b2s[n], bn1 = b2s[n + 1];
                #pragma unroll
                for (int rr = 0; rr < 2; ++rr) {
                    const float x0 = frelu(acc[s][tm][tn][2*rr    ] + bn0);
                    const float x1 = frelu(acc[s][tm][tn][2*rr + 1] + bn1);
                    hh[(m + 8*rr) * 68 + (n >> 1)] =
                        pack2h(__float2half_rn(x0), __float2half_rn(x1));
                }
            }
        }
    }
    CP_ASYNC_WAIT0();
    __syncthreads();

    // ============ layer3: h2[s][128x128] @ W3[128x64], B shared ============
    float acc3[2][2][2][4];   // [s][tm][tp][quad] = 64 f32
    #pragma unroll
    for (int s = 0; s < 2; s++)
        #pragma unroll
        for (int a = 0; a < 2; a++)
            #pragma unroll
            for (int b = 0; b < 2; b++)
                #pragma unroll
                for (int c = 0; c < 4; c++) acc3[s][a][b][c] = 0.0f;

    float acc3n[2][2][2][4];  // second n-half accumulators [s][tm][tp][quad]
    #pragma unroll
    for (int s = 0; s < 2; s++)
        #pragma unroll
        for (int a = 0; a < 2; a++)
            #pragma unroll
            for (int b = 0; b < 2; b++)
                #pragma unroll
                for (int c = 0; c < 4; c++) acc3n[s][a][b][c] = 0.0f;

    #pragma unroll
    for (int ks = 0; ks < 8; ++ks) {
        uint32_t afr[2][2][4];   // [s][tm]
        #pragma unroll
        for (int s = 0; s < 2; ++s)
            #pragma unroll
            for (int tm = 0; tm < 2; ++tm) {
                const int mrow = wm * 32 + tm * 16 + (lane & 7) + 8 * ((lane >> 3) & 1);
                const int kcol = ks * 16 + 8 * (lane >> 4);
                ldsm4(afr[s][tm], sb + SM_H2 + s * H2_S + mrow * 272 + kcol * 2);
            }
        #pragma unroll
        for (int tp = 0; tp < 2; ++tp) {
            uint32_t bh[4];
            const int nrow = wn * 32 + tp * 16 + (lane & 7) + 8 * (lane >> 4);
            const int kcol = ks * 16 + 8 * ((lane >> 3) & 1);
            ldsm4(bh, sb + SM_W3 + nrow * 272 + kcol * 2);
            #pragma unroll
            for (int s = 0; s < 2; ++s)
                #pragma unroll
                for (int tm = 0; tm < 2; ++tm) {
                    mma_f16(acc3[s][tm][tp],  afr[s][tm], &bh[0]);
                    mma_f16(acc3n[s][tm][tp], afr[s][tm], &bh[2]);
                }
        }
    }

    // ============== layer3 epilogue + layer4 (registers + shfl) =============
    #pragma unroll
    for (int s = 0; s < 2; ++s) {
        float part[4] = {0.0f, 0.0f, 0.0f, 0.0f};
        #pragma unroll
        for (int tp = 0; tp < 2; ++tp) {
            const int n0 = wn * 32 + tp * 16 + (lane & 3) * 2;       // first n-half
            const int n1 = n0 + 8;                                    // second n-half
            const float b0a = b3s[n0], b0b = b3s[n0 + 1];
            const float w0a = W4s[n0], w0b = W4s[n0 + 1];
            const float b1a = b3s[n1], b1b = b3s[n1 + 1];
            const float w1a = W4s[n1], w1b = W4s[n1 + 1];
            #pragma unroll
            for (int tm = 0; tm < 2; ++tm)
                #pragma unroll
                for (int rr = 0; rr < 2; ++rr) {
                    part[tm*2 + rr] += frelu(acc3[s][tm][tp][2*rr    ] + b0a) * w0a
                                     + frelu(acc3[s][tm][tp][2*rr + 1] + b0b) * w0b
                                     + frelu(acc3n[s][tm][tp][2*rr    ] + b1a) * w1a
                                     + frelu(acc3n[s][tm][tp][2*rr + 1] + b1b) * w1b;
                }
        }
        #pragma unroll
        for (int i = 0; i < 4; ++i) {
            part[i] += __shfl_xor_sync(0xffffffffu, part[i], 1);
            part[i] += __shfl_xor_sync(0xffffffffu, part[i], 2);
        }
        if ((lane & 3) == 0) {
            #pragma unroll
            for (int tm = 0; tm < 2; ++tm)
                #pragma unroll
                for (int rr = 0; rr < 2; ++rr) {
                    const int m = wm * 32 + tm * 16 + rr * 8 + (lane >> 2);
                    red[s * 256 + wn * 128 + m] = part[tm*2 + rr];
                }
        }
    }
    __syncthreads();
    if (tid < 128) {
        #pragma unroll
        for (int s = 0; s < 2; ++s) {
            const float v = red[s * 256 + tid] + red[s * 256 + 128 + tid] + b4[0];
            out[(q0 + tid) * NS + s0 + s] = 1.0f / (1.0f + expf(-v));
        }
    }
}

// ---------------------------------------------------------------------------
extern "C" void kernel_launch(void* const* d_in, const int* in_sizes, int n_in,
                              void* d_out, int out_size)
{
    const float* qf = (const float*)d_in[0];
    const float* sf = (const float*)d_in[1];
    // d_in[2] = support_y (unused)
    const float* W1 = (const float*)d_in[3];
    const float* b1 = (const float*)d_in[4];
    const float* W2 = (const float*)d_in[5];
    const float* b2 = (const float*)d_in[6];
    const float* W3 = (const float*)d_in[7];
    const float* b3 = (const float*)d_in[8];
    const float* W4 = (const float*)d_in[9];
    const float* b4 = (const float*)d_in[10];
    float* out = (float*)d_out;

    cudaFuncSetAttribute(relation_mma_kernel,
                         cudaFuncAttributeMaxDynamicSharedMemorySize, SMEM_TOTAL);
    cudaFuncSetAttribute(precompute_mma_kernel,
                         cudaFuncAttributeMaxDynamicSharedMemorySize, PRE_SMEM_TOTAL);

    prep_w1_kernel<<<512, 256>>>(W1);
    precompute_mma_kernel<<<dim3(15, 2), 256, PRE_SMEM_TOTAL>>>(qf, sf, b1, W2, W3);
    relation_mma_kernel<<<dim3(NS / 2, NQ / TM), 256, SMEM_TOTAL>>>(b2, b3, W4, b4, out);
}

// round 14
// speedup vs baseline: 1.1341x; 1.1341x over previous
#include <cuda_runtime.h>
#include <cuda_fp16.h>
#include <math.h>
#include <stdint.h>

#define NQ 1024
#define NS 256
#define E  256
#define H1 256
#define H2 128
#define H3 64
#define TM 128          // query rows per CTA

// ---------------- warp-MMA helpers (plain sm_80+ PTX) -----------------------
__device__ __forceinline__ uint32_t smem_to_u32(const void* p) {
    uint32_t a;
    asm("{ .reg .u64 t; cvta.to.shared.u64 t, %1; cvt.u32.u64 %0, t; }" : "=r"(a) : "l"(p));
    return a;
}
__device__ __forceinline__ void ldsm4(uint32_t* r, uint32_t addr) {
    asm volatile("ldmatrix.sync.aligned.m8n8.x4.shared.b16 {%0,%1,%2,%3}, [%4];"
                 : "=r"(r[0]), "=r"(r[1]), "=r"(r[2]), "=r"(r[3]) : "r"(addr));
}
__device__ __forceinline__ void mma_f16(float* d, const uint32_t* a, const uint32_t* b) {
    asm volatile("mma.sync.aligned.m16n8k16.row.col.f32.f16.f16.f32 "
                 "{%0,%1,%2,%3}, {%4,%5,%6,%7}, {%8,%9}, {%0,%1,%2,%3};"
                 : "+f"(d[0]), "+f"(d[1]), "+f"(d[2]), "+f"(d[3])
                 : "r"(a[0]), "r"(a[1]), "r"(a[2]), "r"(a[3]), "r"(b[0]), "r"(b[1]));
}
__device__ __forceinline__ void cp_async16(uint32_t dst_smem, const void* src) {
    asm volatile("cp.async.cg.shared.global [%0], [%1], 16;"
                 :: "r"(dst_smem), "l"(src));
}
#define CP_ASYNC_COMMIT() asm volatile("cp.async.commit_group;" ::: "memory")
#define CP_ASYNC_WAIT0()  asm volatile("cp.async.wait_group 0;" ::: "memory")

__device__ __forceinline__ void split_f16(float x, __half& hi, __half& lo) {
    hi = __float2half_rn(x);
    lo = __float2half_rn(x - __half2float(hi));
}
__device__ __forceinline__ uint32_t pack2h(__half a, __half b) {
    __half2 t; t.x = a; t.y = b;
    return *reinterpret_cast<uint32_t*>(&t);
}
__device__ __forceinline__ uint32_t hadd2_relu(uint32_t a, uint32_t b) {
    __half2 r = __hmax2(__hadd2(*reinterpret_cast<__half2*>(&a),
                                *reinterpret_cast<__half2*>(&b)),
                        __half2(__half(0.0f), __half(0.0f)));
    return *reinterpret_cast<uint32_t*>(&r);
}
__device__ __forceinline__ float frelu(float x) { return fmaxf(x, 0.0f); }

// ---------------- global scratch (static) -----------------------------------
__device__ uint4  g_QpF[16 * 64 * 32];        // [K16][M16][lane] fp16 A-fragments
__device__ float  g_Sp [NS * H1];             // [s][k] (+b1)
__device__ __half g_W2TB[128 * 264];          // [n][264k] fp16, k<256 data
__device__ __half g_W3TB[8704];               // [n*136+k] fp16

// ---------------- main-kernel smem layout (bytes) ----------------------------
#define SM_W2   0         // whole W2^T [128n][264k] fp16 = 67584
#define SM_W3   0         // phase B: W3^T [64n][136k] = 17408 (aliases SM_W2)
#define SM_H2   67584     // h2 fp16 [128m][136k] = 34816 (ends 102400)
#define SM_SP16 102400    // 256 fp16 = 512
#define SM_B2S  102912    // 128 f32
#define SM_B3S  103424    // 64 f32
#define SM_W4S  103680    // 64 f32
#define SM_RED  103936    // 2*128 f32 = 1024
#define SMEM_TOTAL 104960

// ---------------- precompute-kernel smem layout ------------------------------
#define PSM_A  0          // feat fp16 [128m][264k] = 67584
#define PSM_B  67584      // W1 stage: 2 x (hi 10240 + lo 10240) = 40960
#define PB_STRIDE 20480
#define PRE_SMEM_TOTAL 108544

// ---------------------------------------------------------------------------
// Precompute via mma: Qp -> g_QpF fragments; Sp -> g_Sp.
// W1 converted fp32->fp16 hi/lo INLINE while staging (no prep kernel,
// no global fp16 W1 tables). Double-buffered: convert c+1 during mma of c.
// mb 0..9: GEMM CTAs. mb 10..14: W2/W3 fp16 conversion (runs concurrently).
// ---------------------------------------------------------------------------
__global__ void __launch_bounds__(256)
precompute_mma_kernel(const float* __restrict__ qf,
                      const float* __restrict__ sf,
                      const float* __restrict__ b1,
                      const float* __restrict__ W1,
                      const float* __restrict__ W2,
                      const float* __restrict__ W3)
{
    const int mb = blockIdx.x;         // 0..14
    const int nb = blockIdx.y;         // 0..1

    if (mb >= 10) {
        // ---- conversion CTAs: W2 -> g_W2TB, W3 -> g_W3TB ----
        const int cid = (mb - 10) * 2 + nb;     // 0..9
        for (int e = cid * 256 + threadIdx.x; e < 33792 + 8704; e += 2560) {
            if (e < 33792) {
                const int n = e / 264, k = e % 264;
                const float w = (k < 256) ? W2[k * H2 + n] : 0.0f;
                g_W2TB[e] = __float2half_rn(w);
            } else {
                const int t = e - 33792;
                const int n = t / 136, k = t % 136;
                const float w = (k < 128) ? W3[k * H3 + n] : 0.0f;
                g_W3TB[t] = __float2half_rn(w);
            }
        }
        return;
    }

    extern __shared__ char smem[];
    const uint32_t sb = smem_to_u32(smem);
    const int tid  = threadIdx.x;
    const int lane = tid & 31;
    const int wid  = tid >> 5;
    const int wm   = wid & 3;
    const int wn   = wid >> 2;
    const bool isQ = (mb < 8);
    const float* feat = isQ ? (qf + mb * 128 * E) : (sf + (mb - 8) * 128 * E);
    const int hf = isQ ? 0 : 1;

    // inline W1 chunk conversion: chunk c covers k rows hf*256+c*32+[0,32),
    // cols nb*128+[0,128). Thread t: n = t&127, kk base = (t>>7)*2, step 4.
    const int cv_n   = tid & 127;
    const int cv_kkb = (tid >> 7) * 2;
    const float* W1base = W1 + (hf * 256) * H1 + nb * 128 + cv_n;

    // ---- stage A: feat[128][256] f32 -> fp16 smem [128][264] ----
    {
        const int row = tid >> 1, hv = tid & 1;
        const float4* src = reinterpret_cast<const float4*>(feat + row * E);
        uint32_t* dst = reinterpret_cast<uint32_t*>(smem + PSM_A);
        #pragma unroll 8
        for (int j = 0; j < 32; ++j) {
            const float4 v = src[hv * 32 + j];
            const int u = row * 132 + (hv * 32 + j) * 2;
            dst[u]     = pack2h(__float2half_rn(v.x), __float2half_rn(v.y));
            dst[u + 1] = pack2h(__float2half_rn(v.z), __float2half_rn(v.w));
        }
    }
    // ---- prologue: convert W1 chunk 0 into buf 0 ----
    {
        uint32_t* bufH = reinterpret_cast<uint32_t*>(smem + PSM_B);
        uint32_t* bufL = reinterpret_cast<uint32_t*>(smem + PSM_B + 10240);
        #pragma unroll
        for (int i = 0; i < 8; ++i) {
            const int kk = cv_kkb + i * 4;
            const float w0 = W1base[(0 * 32 + kk    ) * H1];
            const float w1 = W1base[(0 * 32 + kk + 1) * H1];
            __half h0, l0, h1, l1;
            split_f16(w0, h0, l0);
            split_f16(w1, h1, l1);
            bufH[(cv_n * 80 + kk * 2) >> 2] = pack2h(h0, h1);
            bufL[(cv_n * 80 + kk * 2) >> 2] = pack2h(l0, l1);
        }
    }
    __syncthreads();

    float acc[2][8][4];
    #pragma unroll
    for (int a = 0; a < 2; a++)
        #pragma unroll
        for (int b = 0; b < 8; b++)
            #pragma unroll
            for (int c = 0; c < 4; c++) acc[a][b][c] = 0.0f;

    for (int c = 0; c < 8; ++c) {
        const int st = c & 1;
        if (c < 7) {
            // convert chunk c+1 into the other buffer (overlaps mma below)
            uint32_t* bufH = reinterpret_cast<uint32_t*>(smem + PSM_B + (st ^ 1) * PB_STRIDE);
            uint32_t* bufL = reinterpret_cast<uint32_t*>(smem + PSM_B + (st ^ 1) * PB_STRIDE + 10240);
            #pragma unroll
            for (int i = 0; i < 8; ++i) {
                const int kk = cv_kkb + i * 4;
                const float w0 = W1base[((c + 1) * 32 + kk    ) * H1];
                const float w1 = W1base[((c + 1) * 32 + kk + 1) * H1];
                __half h0, l0, h1, l1;
                split_f16(w0, h0, l0);
                split_f16(w1, h1, l1);
                bufH[(cv_n * 80 + kk * 2) >> 2] = pack2h(h0, h1);
                bufL[(cv_n * 80 + kk * 2) >> 2] = pack2h(l0, l1);
            }
        }
        const uint32_t bufH = sb + PSM_B + st * PB_STRIDE;
        #pragma unroll
        for (int ks = 0; ks < 2; ++ks) {
            uint32_t afr[2][4];
            #pragma unroll
            for (int tm = 0; tm < 2; ++tm) {
                const int mrow = wm * 32 + tm * 16 + (lane & 7) + 8 * ((lane >> 3) & 1);
                const int kcol = c * 32 + ks * 16 + 8 * (lane >> 4);
                ldsm4(afr[tm], sb + PSM_A + mrow * 528 + kcol * 2);
            }
            #pragma unroll
            for (int tp = 0; tp < 4; ++tp) {
                uint32_t bh[4], bl[4];
                const int nrow = wn * 64 + tp * 16 + (lane & 7) + 8 * (lane >> 4);
                const int kcol = ks * 16 + 8 * ((lane >> 3) & 1);
                const uint32_t baddr = bufH + nrow * 80 + kcol * 2;
                ldsm4(bh, baddr);
                ldsm4(bl, baddr + 10240);
                #pragma unroll
                for (int tm = 0; tm < 2; ++tm) {
                    mma_f16(acc[tm][2*tp    ], afr[tm], &bh[0]);
                    mma_f16(acc[tm][2*tp    ], afr[tm], &bl[0]);
                    mma_f16(acc[tm][2*tp + 1], afr[tm], &bh[2]);
                    mma_f16(acc[tm][2*tp + 1], afr[tm], &bl[2]);
                }
            }
        }
        __syncthreads();   // mma reads of buf[st] done; converts of buf[st^1] visible
    }

    // ---- epilogue ----
    if (isQ) {
        #pragma unroll
        for (int tm = 0; tm < 2; ++tm)
            #pragma unroll
            for (int tnp = 0; tnp < 4; ++tnp) {
                const int K16 = nb * 8 + wn * 4 + tnp;
                const int M16 = mb * 8 + wm * 2 + tm;
                uint4 v;
                v.x = pack2h(__float2half_rn(acc[tm][2*tnp][0]),
                             __float2half_rn(acc[tm][2*tnp][1]));
                v.y = pack2h(__float2half_rn(acc[tm][2*tnp][2]),
                             __float2half_rn(acc[tm][2*tnp][3]));
                v.z = pack2h(__float2half_rn(acc[tm][2*tnp+1][0]),
                             __float2half_rn(acc[tm][2*tnp+1][1]));
                v.w = pack2h(__float2half_rn(acc[tm][2*tnp+1][2]),
                             __float2half_rn(acc[tm][2*tnp+1][3]));
                g_QpF[(K16 * 64 + M16) * 32 + lane] = v;
            }
    } else {
        const int s0 = (mb - 8) * 128;
        #pragma unroll
        for (int tm = 0; tm < 2; ++tm)
            #pragma unroll
            for (int tn = 0; tn < 8; ++tn) {
                const int n = nb * 128 + wn * 64 + tn * 8 + (lane & 3) * 2;
                const float bb0 = b1[n], bb1 = b1[n + 1];
                #pragma unroll
                for (int rr = 0; rr < 2; ++rr) {
                    const int m = wm * 32 + tm * 16 + rr * 8 + (lane >> 2);
                    g_Sp[(s0 + m) * H1 + n]     = acc[tm][tn][2*rr]     + bb0;
                    g_Sp[(s0 + m) * H1 + n + 1] = acc[tm][tn][2*rr + 1] + bb1;
                }
            }
    }
}

// ---------------------------------------------------------------------------
// Fused MLP (R9/R11 winner, unchanged): whole W2 resident; barrier-free
// layer2 mainloop; register-fragment A (relu(Qp+Sp) via HADD2/HMAX2).
// ---------------------------------------------------------------------------
__global__ void __launch_bounds__(256, 2)
relation_mma_kernel(const float* __restrict__ b2,
                    const float* __restrict__ b3,
                    const float* __restrict__ W4,
                    const float* __restrict__ b4,
                    float* __restrict__ out)
{
    extern __shared__ char smem[];
    const uint32_t sb = smem_to_u32(smem);
    const int tid  = threadIdx.x;
    const int lane = tid & 31;
    const int wid  = tid >> 5;
    const int wm   = wid & 3;
    const int wn   = wid >> 2;
    const int s_idx = blockIdx.x;
    const int q0    = blockIdx.y * TM;
    const int M16b  = blockIdx.y * 8 + wm * 2;

    float* b2s = (float*)(smem + SM_B2S);
    float* b3s = (float*)(smem + SM_B3S);
    float* W4s = (float*)(smem + SM_W4S);
    float* red = (float*)(smem + SM_RED);
    __half* sp16 = (__half*)(smem + SM_SP16);

    sp16[tid] = __float2half_rn(g_Sp[s_idx * H1 + tid]);
    if (tid < H2) b2s[tid] = b2[tid];
    if (tid < H3) { b3s[tid] = b3[tid]; W4s[tid] = W4[tid]; }

    // ---- prologue: cp.async the WHOLE W2 (67584 B = 4224 x 16B) ----
    {
        const char* src = (const char*)g_W2TB;
        #pragma unroll
        for (int i = 0; i < 17; ++i) {
            const int t = tid + 256 * i;
            if (t < 4224) cp_async16(sb + SM_W2 + t * 16, src + t * 16);
        }
        CP_ASYNC_COMMIT();
    }
    uint4 aq[2][2];
    #pragma unroll
    for (int tm = 0; tm < 2; ++tm)
        #pragma unroll
        for (int ks = 0; ks < 2; ++ks)
            aq[tm][ks] = g_QpF[(ks * 64 + M16b + tm) * 32 + lane];

    float acc[2][8][4];
    #pragma unroll
    for (int a = 0; a < 2; a++)
        #pragma unroll
        for (int b = 0; b < 8; b++)
            #pragma unroll
            for (int c = 0; c < 4; c++) acc[a][b][c] = 0.0f;

    CP_ASYNC_WAIT0();
    __syncthreads();   // W2 + sp16 + biases visible; only barrier before loop

    // ============ layer2 mainloop: 8 chunks of k=32, barrier-free ===========
    #pragma unroll
    for (int c = 0; c < 8; ++c) {
        uint32_t af[2][2][4];
        #pragma unroll
        for (int ks = 0; ks < 2; ++ks) {
            const uint32_t spA = *(const uint32_t*)(smem + SM_SP16 + c * 64 + ks * 32 + (lane & 3) * 4);
            const uint32_t spB = *(const uint32_t*)(smem + SM_SP16 + c * 64 + ks * 32 + (lane & 3) * 4 + 16);
            #pragma unroll
            for (int tm = 0; tm < 2; ++tm) {
                af[tm][ks][0] = hadd2_relu(aq[tm][ks].x, spA);
                af[tm][ks][1] = hadd2_relu(aq[tm][ks].y, spA);
                af[tm][ks][2] = hadd2_relu(aq[tm][ks].z, spB);
                af[tm][ks][3] = hadd2_relu(aq[tm][ks].w, spB);
            }
        }
        if (c < 7) {
            #pragma unroll
            for (int tm = 0; tm < 2; ++tm)
                #pragma unroll
                for (int ks = 0; ks < 2; ++ks)
                    aq[tm][ks] = g_QpF[(((c + 1) * 2 + ks) * 64 + M16b + tm) * 32 + lane];
        }
        #pragma unroll
        for (int ks = 0; ks < 2; ++ks) {
            #pragma unroll
            for (int tp = 0; tp < 4; ++tp) {
                uint32_t bh[4];
                const int nrow = wn * 64 + tp * 16 + (lane & 7) + 8 * (lane >> 4);
                const int kcol = c * 32 + ks * 16 + 8 * ((lane >> 3) & 1);
                ldsm4(bh, sb + SM_W2 + nrow * 528 + kcol * 2);
                #pragma unroll
                for (int tm = 0; tm < 2; ++tm) {
                    mma_f16(acc[tm][2*tp    ], af[tm][ks], &bh[0]);
                    mma_f16(acc[tm][2*tp + 1], af[tm][ks], &bh[2]);
                }
            }
        }
    }
    __syncthreads();   // all W2 reads done CTA-wide; W2 region reusable

    // stage W3^T into W2's region via cp.async (overlaps epilogue below)
    {
        const char* srcH = (const char*)g_W3TB;
        #pragma unroll
        for (int i = 0; i < 5; ++i) {
            const int t = tid + 256 * i;
            if (t < 1088) cp_async16(sb + SM_W3 + t * 16, srcH + t * 16);
        }
        CP_ASYNC_COMMIT();
    }
    // layer2 epilogue: bias+relu -> fp16 -> h2[m][k]
    {
        uint32_t* hh = reinterpret_cast<uint32_t*>(smem + SM_H2);
        #pragma unroll
        for (int tm = 0; tm < 2; ++tm) {
            #pragma unroll
            for (int tn = 0; tn < 8; ++tn) {
                const int n = wn * 64 + tn * 8 + (lane & 3) * 2;
                const int m = wm * 32 + tm * 16 + (lane >> 2);
                const float bn0 = b2s[n], bn1 = b2s[n + 1];
                #pragma unroll
                for (int rr = 0; rr < 2; ++rr) {
                    const float x0 = frelu(acc[tm][tn][2*rr    ] + bn0);
                    const float x1 = frelu(acc[tm][tn][2*rr + 1] + bn1);
                    hh[(m + 8*rr) * 68 + (n >> 1)] =
                        pack2h(__float2half_rn(x0), __float2half_rn(x1));
                }
            }
        }
    }
    CP_ASYNC_WAIT0();
    __syncthreads();

    // =================== layer3: h2[128x128] @ W3[128x64] ===================
    float acc3[2][4][4];
    #pragma unroll
    for (int a = 0; a < 2; a++)
        #pragma unroll
        for (int b = 0; b < 4; b++)
            #pragma unroll
            for (int c = 0; c < 4; c++) acc3[a][b][c] = 0.0f;

    #pragma unroll
    for (int ks = 0; ks < 8; ++ks) {
        uint32_t afr[2][4];
        #pragma unroll
        for (int tm = 0; tm < 2; ++tm) {
            const int mrow = wm * 32 + tm * 16 + (lane & 7) + 8 * ((lane >> 3) & 1);
            const int kcol = ks * 16 + 8 * (lane >> 4);
            ldsm4(afr[tm], sb + SM_H2 + mrow * 272 + kcol * 2);
        }
        #pragma unroll
        for (int tp = 0; tp < 2; ++tp) {
            uint32_t bh[4];
            const int nrow = wn * 32 + tp * 16 + (lane & 7) + 8 * (lane >> 4);
            const int kcol = ks * 16 + 8 * ((lane >> 3) & 1);
            ldsm4(bh, sb + SM_W3 + nrow * 272 + kcol * 2);
            #pragma unroll
            for (int tm = 0; tm < 2; ++tm) {
                mma_f16(acc3[tm][2*tp    ], afr[tm], &bh[0]);
                mma_f16(acc3[tm][2*tp + 1], afr[tm], &bh[2]);
            }
        }
    }

    // ============== layer3 epilogue + layer4 (registers + shfl) =============
    float part[4] = {0.0f, 0.0f, 0.0f, 0.0f};
    #pragma unroll
    for (int tn = 0; tn < 4; ++tn) {
        const int n = wn * 32 + tn * 8 + (lane & 3) * 2;
        const float bn0 = b3s[n], bn1 = b3s[n + 1];
        const float w0 = W4s[n],  w1 = W4s[n + 1];
        #pragma unroll
        for (int tm = 0; tm < 2; ++tm) {
            #pragma unroll
            for (int rr = 0; rr < 2; ++rr) {
                part[tm*2 + rr] += frelu(acc3[tm][tn][2*rr    ] + bn0) * w0
                                 + frelu(acc3[tm][tn][2*rr + 1] + bn1) * w1;
            }
        }
    }
    #pragma unroll
    for (int i = 0; i < 4; ++i) {
        part[i] += __shfl_xor_sync(0xffffffffu, part[i], 1);
        part[i] += __shfl_xor_sync(0xffffffffu, part[i], 2);
    }
    if ((lane & 3) == 0) {
        #pragma unroll
        for (int tm = 0; tm < 2; ++tm)
            #pragma unroll
            for (int rr = 0; rr < 2; ++rr) {
                const int m = wm * 32 + tm * 16 + rr * 8 + (lane >> 2);
                red[wn * 128 + m] = part[tm*2 + rr];
            }
    }
    __syncthreads();
    if (tid < 128) {
        const float v = red[tid] + red[128 + tid] + b4[0];
        out[(q0 + tid) * NS + s_idx] = 1.0f / (1.0f + expf(-v));
    }
}

// ---------------------------------------------------------------------------
extern "C" void kernel_launch(void* const* d_in, const int* in_sizes, int n_in,
                              void* d_out, int out_size)
{
    const float* qf = (const float*)d_in[0];
    const float* sf = (const float*)d_in[1];
    // d_in[2] = support_y (unused)
    const float* W1 = (const float*)d_in[3];
    const float* b1 = (const float*)d_in[4];
    const float* W2 = (const float*)d_in[5];
    const float* b2 = (const float*)d_in[6];
    const float* W3 = (const float*)d_in[7];
    const float* b3 = (const float*)d_in[8];
    const float* W4 = (const float*)d_in[9];
    const float* b4 = (const float*)d_in[10];
    float* out = (float*)d_out;

    cudaFuncSetAttribute(relation_mma_kernel,
                         cudaFuncAttributeMaxDynamicSharedMemorySize, SMEM_TOTAL);
    cudaFuncSetAttribute(precompute_mma_kernel,
                         cudaFuncAttributeMaxDynamicSharedMemorySize, PRE_SMEM_TOTAL);

    precompute_mma_kernel<<<dim3(15, 2), 256, PRE_SMEM_TOTAL>>>(qf, sf, b1, W1, W2, W3);
    relation_mma_kernel<<<dim3(NS, NQ / TM), 256, SMEM_TOTAL>>>(b2, b3, W4, b4, out);
}

// round 15
// speedup vs baseline: 1.1467x; 1.0110x over previous
#include <cuda_runtime.h>
#include <cuda_fp16.h>
#include <math.h>
#include <stdint.h>

#define NQ 1024
#define NS 256
#define E  256
#define H1 256
#define H2 128
#define H3 64
#define TM 128          // query rows per CTA

// ---------------- warp-MMA helpers (plain sm_80+ PTX) -----------------------
__device__ __forceinline__ uint32_t smem_to_u32(const void* p) {
    uint32_t a;
    asm("{ .reg .u64 t; cvta.to.shared.u64 t, %1; cvt.u32.u64 %0, t; }" : "=r"(a) : "l"(p));
    return a;
}
__device__ __forceinline__ void ldsm4(uint32_t* r, uint32_t addr) {
    asm volatile("ldmatrix.sync.aligned.m8n8.x4.shared.b16 {%0,%1,%2,%3}, [%4];"
                 : "=r"(r[0]), "=r"(r[1]), "=r"(r[2]), "=r"(r[3]) : "r"(addr));
}
__device__ __forceinline__ void mma_f16(float* d, const uint32_t* a, const uint32_t* b) {
    asm volatile("mma.sync.aligned.m16n8k16.row.col.f32.f16.f16.f32 "
                 "{%0,%1,%2,%3}, {%4,%5,%6,%7}, {%8,%9}, {%0,%1,%2,%3};"
                 : "+f"(d[0]), "+f"(d[1]), "+f"(d[2]), "+f"(d[3])
                 : "r"(a[0]), "r"(a[1]), "r"(a[2]), "r"(a[3]), "r"(b[0]), "r"(b[1]));
}
__device__ __forceinline__ void cp_async16(uint32_t dst_smem, const void* src) {
    asm volatile("cp.async.cg.shared.global [%0], [%1], 16;"
                 :: "r"(dst_smem), "l"(src));
}
#define CP_ASYNC_COMMIT() asm volatile("cp.async.commit_group;" ::: "memory")
#define CP_ASYNC_WAIT0()  asm volatile("cp.async.wait_group 0;" ::: "memory")

__device__ __forceinline__ void split_f16(float x, __half& hi, __half& lo) {
    hi = __float2half_rn(x);
    lo = __float2half_rn(x - __half2float(hi));
}
__device__ __forceinline__ uint32_t pack2h(__half a, __half b) {
    __half2 t; t.x = a; t.y = b;
    return *reinterpret_cast<uint32_t*>(&t);
}
// relu(a + b) in ONE instruction: HFMA2.RELU (a*1 + b, exact, fused relu)
__device__ __forceinline__ uint32_t hadd2_relu(uint32_t a, uint32_t b) {
    const __half2 one = __half2(__half(1.0f), __half(1.0f));
    __half2 r = __hfma2_relu(*reinterpret_cast<__half2*>(&a), one,
                             *reinterpret_cast<__half2*>(&b));
    return *reinterpret_cast<uint32_t*>(&r);
}
__device__ __forceinline__ float frelu(float x) { return fmaxf(x, 0.0f); }

// ---------------- global scratch (static) -----------------------------------
__device__ uint4  g_QpF[16 * 64 * 32];        // [K16][M16][lane] fp16 A-fragments
__device__ float  g_Sp [NS * H1];             // [s][k] (+b1)
__device__ __half g_W2TB[128 * 264];          // [n][264k] fp16, k<256 data
__device__ __half g_W3TB[8704];               // [n*136+k] fp16

// ---------------- main-kernel smem layout (bytes) ----------------------------
#define SM_W2   0         // whole W2^T [128n][264k] fp16 = 67584
#define SM_W3   0         // phase B: W3^T [64n][136k] = 17408 (aliases SM_W2)
#define SM_H2   67584     // h2 fp16 [128m][136k] = 34816 (ends 102400)
#define SM_SP16 102400    // 256 fp16 = 512
#define SM_B2S  102912    // 128 f32
#define SM_B3S  103424    // 64 f32
#define SM_W4S  103680    // 64 f32
#define SM_RED  103936    // 2*128 f32 = 1024
#define SMEM_TOTAL 104960

// ---------------- precompute-kernel smem layout ------------------------------
#define PSM_A  0          // feat fp16 [128m][264k] = 67584
#define PSM_B  67584      // W1 stage: 2 x (hi 10240 + lo 10240) = 40960
#define PB_STRIDE 20480
#define PRE_SMEM_TOTAL 108544

// ---------------------------------------------------------------------------
// Precompute via mma: Qp -> g_QpF fragments; Sp -> g_Sp. W1 converted inline.
// mb 0..9: GEMM CTAs. mb 10..14: W2/W3 fp16 conversion (runs concurrently).
// ---------------------------------------------------------------------------
__global__ void __launch_bounds__(256)
precompute_mma_kernel(const float* __restrict__ qf,
                      const float* __restrict__ sf,
                      const float* __restrict__ b1,
                      const float* __restrict__ W1,
                      const float* __restrict__ W2,
                      const float* __restrict__ W3)
{
    const int mb = blockIdx.x;         // 0..14
    const int nb = blockIdx.y;         // 0..1

    if (mb >= 10) {
        const int cid = (mb - 10) * 2 + nb;     // 0..9
        for (int e = cid * 256 + threadIdx.x; e < 33792 + 8704; e += 2560) {
            if (e < 33792) {
                const int n = e / 264, k = e % 264;
                const float w = (k < 256) ? W2[k * H2 + n] : 0.0f;
                g_W2TB[e] = __float2half_rn(w);
            } else {
                const int t = e - 33792;
                const int n = t / 136, k = t % 136;
                const float w = (k < 128) ? W3[k * H3 + n] : 0.0f;
                g_W3TB[t] = __float2half_rn(w);
            }
        }
        return;
    }

    extern __shared__ char smem[];
    const uint32_t sb = smem_to_u32(smem);
    const int tid  = threadIdx.x;
    const int lane = tid & 31;
    const int wid  = tid >> 5;
    const int wm   = wid & 3;
    const int wn   = wid >> 2;
    const bool isQ = (mb < 8);
    const float* feat = isQ ? (qf + mb * 128 * E) : (sf + (mb - 8) * 128 * E);
    const int hf = isQ ? 0 : 1;

    const int cv_n   = tid & 127;
    const int cv_kkb = (tid >> 7) * 2;
    const float* W1base = W1 + (hf * 256) * H1 + nb * 128 + cv_n;

    // ---- stage A: feat[128][256] f32 -> fp16 smem [128][264] ----
    {
        const int row = tid >> 1, hv = tid & 1;
        const float4* src = reinterpret_cast<const float4*>(feat + row * E);
        uint32_t* dst = reinterpret_cast<uint32_t*>(smem + PSM_A);
        #pragma unroll 8
        for (int j = 0; j < 32; ++j) {
            const float4 v = src[hv * 32 + j];
            const int u = row * 132 + (hv * 32 + j) * 2;
            dst[u]     = pack2h(__float2half_rn(v.x), __float2half_rn(v.y));
            dst[u + 1] = pack2h(__float2half_rn(v.z), __float2half_rn(v.w));
        }
    }
    // ---- prologue: convert W1 chunk 0 into buf 0 ----
    {
        uint32_t* bufH = reinterpret_cast<uint32_t*>(smem + PSM_B);
        uint32_t* bufL = reinterpret_cast<uint32_t*>(smem + PSM_B + 10240);
        #pragma unroll
        for (int i = 0; i < 8; ++i) {
            const int kk = cv_kkb + i * 4;
            const float w0 = W1base[(0 * 32 + kk    ) * H1];
            const float w1 = W1base[(0 * 32 + kk + 1) * H1];
            __half h0, l0, h1, l1;
            split_f16(w0, h0, l0);
            split_f16(w1, h1, l1);
            bufH[(cv_n * 80 + kk * 2) >> 2] = pack2h(h0, h1);
            bufL[(cv_n * 80 + kk * 2) >> 2] = pack2h(l0, l1);
        }
    }
    __syncthreads();

    float acc[2][8][4];
    #pragma unroll
    for (int a = 0; a < 2; a++)
        #pragma unroll
        for (int b = 0; b < 8; b++)
            #pragma unroll
            for (int c = 0; c < 4; c++) acc[a][b][c] = 0.0f;

    for (int c = 0; c < 8; ++c) {
        const int st = c & 1;
        if (c < 7) {
            uint32_t* bufH = reinterpret_cast<uint32_t*>(smem + PSM_B + (st ^ 1) * PB_STRIDE);
            uint32_t* bufL = reinterpret_cast<uint32_t*>(smem + PSM_B + (st ^ 1) * PB_STRIDE + 10240);
            #pragma unroll
            for (int i = 0; i < 8; ++i) {
                const int kk = cv_kkb + i * 4;
                const float w0 = W1base[((c + 1) * 32 + kk    ) * H1];
                const float w1 = W1base[((c + 1) * 32 + kk + 1) * H1];
                __half h0, l0, h1, l1;
                split_f16(w0, h0, l0);
                split_f16(w1, h1, l1);
                bufH[(cv_n * 80 + kk * 2) >> 2] = pack2h(h0, h1);
                bufL[(cv_n * 80 + kk * 2) >> 2] = pack2h(l0, l1);
            }
        }
        const uint32_t bufH = sb + PSM_B + st * PB_STRIDE;
        #pragma unroll
        for (int ks = 0; ks < 2; ++ks) {
            uint32_t afr[2][4];
            #pragma unroll
            for (int tm = 0; tm < 2; ++tm) {
                const int mrow = wm * 32 + tm * 16 + (lane & 7) + 8 * ((lane >> 3) & 1);
                const int kcol = c * 32 + ks * 16 + 8 * (lane >> 4);
                ldsm4(afr[tm], sb + PSM_A + mrow * 528 + kcol * 2);
            }
            #pragma unroll
            for (int tp = 0; tp < 4; ++tp) {
                uint32_t bh[4], bl[4];
                const int nrow = wn * 64 + tp * 16 + (lane & 7) + 8 * (lane >> 4);
                const int kcol = ks * 16 + 8 * ((lane >> 3) & 1);
                const uint32_t baddr = bufH + nrow * 80 + kcol * 2;
                ldsm4(bh, baddr);
                ldsm4(bl, baddr + 10240);
                #pragma unroll
                for (int tm = 0; tm < 2; ++tm) {
                    mma_f16(acc[tm][2*tp    ], afr[tm], &bh[0]);
                    mma_f16(acc[tm][2*tp    ], afr[tm], &bl[0]);
                    mma_f16(acc[tm][2*tp + 1], afr[tm], &bh[2]);
                    mma_f16(acc[tm][2*tp + 1], afr[tm], &bl[2]);
                }
            }
        }
        __syncthreads();   // mma reads of buf[st] done; converts of buf[st^1] visible
    }

    // ---- epilogue ----
    if (isQ) {
        #pragma unroll
        for (int tm = 0; tm < 2; ++tm)
            #pragma unroll
            for (int tnp = 0; tnp < 4; ++tnp) {
                const int K16 = nb * 8 + wn * 4 + tnp;
                const int M16 = mb * 8 + wm * 2 + tm;
                uint4 v;
                v.x = pack2h(__float2half_rn(acc[tm][2*tnp][0]),
                             __float2half_rn(acc[tm][2*tnp][1]));
                v.y = pack2h(__float2half_rn(acc[tm][2*tnp][2]),
                             __float2half_rn(acc[tm][2*tnp][3]));
                v.z = pack2h(__float2half_rn(acc[tm][2*tnp+1][0]),
                             __float2half_rn(acc[tm][2*tnp+1][1]));
                v.w = pack2h(__float2half_rn(acc[tm][2*tnp+1][2]),
                             __float2half_rn(acc[tm][2*tnp+1][3]));
                g_QpF[(K16 * 64 + M16) * 32 + lane] = v;
            }
    } else {
        const int s0 = (mb - 8) * 128;
        #pragma unroll
        for (int tm = 0; tm < 2; ++tm)
            #pragma unroll
            for (int tn = 0; tn < 8; ++tn) {
                const int n = nb * 128 + wn * 64 + tn * 8 + (lane & 3) * 2;
                const float bb0 = b1[n], bb1 = b1[n + 1];
                #pragma unroll
                for (int rr = 0; rr < 2; ++rr) {
                    const int m = wm * 32 + tm * 16 + rr * 8 + (lane >> 2);
                    g_Sp[(s0 + m) * H1 + n]     = acc[tm][tn][2*rr]     + bb0;
                    g_Sp[(s0 + m) * H1 + n + 1] = acc[tm][tn][2*rr + 1] + bb1;
                }
            }
    }
}

// ---------------------------------------------------------------------------
// Fused MLP. R14: HFMA2.RELU single-instruction A-fragment build + immediate-
// offset aq prefetch (two hoisted base pointers, K16 stride = 2048 uint4).
// ---------------------------------------------------------------------------
__global__ void __launch_bounds__(256, 2)
relation_mma_kernel(const float* __restrict__ b2,
                    const float* __restrict__ b3,
                    const float* __restrict__ W4,
                    const float* __restrict__ b4,
                    float* __restrict__ out)
{
    extern __shared__ char smem[];
    const uint32_t sb = smem_to_u32(smem);
    const int tid  = threadIdx.x;
    const int lane = tid & 31;
    const int wid  = tid >> 5;
    const int wm   = wid & 3;
    const int wn   = wid >> 2;
    const int s_idx = blockIdx.x;
    const int q0    = blockIdx.y * TM;
    const int M16b  = blockIdx.y * 8 + wm * 2;

    float* b2s = (float*)(smem + SM_B2S);
    float* b3s = (float*)(smem + SM_B3S);
    float* W4s = (float*)(smem + SM_W4S);
    float* red = (float*)(smem + SM_RED);
    __half* sp16 = (__half*)(smem + SM_SP16);

    sp16[tid] = __float2half_rn(g_Sp[s_idx * H1 + tid]);
    if (tid < H2) b2s[tid] = b2[tid];
    if (tid < H3) { b3s[tid] = b3[tid]; W4s[tid] = W4[tid]; }

    // ---- prologue: cp.async the WHOLE W2 (67584 B = 4224 x 16B) ----
    {
        const char* src = (const char*)g_W2TB;
        #pragma unroll
        for (int i = 0; i < 17; ++i) {
            const int t = tid + 256 * i;
            if (t < 4224) cp_async16(sb + SM_W2 + t * 16, src + t * 16);
        }
        CP_ASYNC_COMMIT();
    }
    // hoisted fragment base pointers; chunk/ks become constant offsets
    const uint4* qbase0 = &g_QpF[(M16b    ) * 32 + lane];
    const uint4* qbase1 = &g_QpF[(M16b + 1) * 32 + lane];
    uint4 aq[2][2];
    #pragma unroll
    for (int ks = 0; ks < 2; ++ks) {
        aq[0][ks] = qbase0[ks * 2048];
        aq[1][ks] = qbase1[ks * 2048];
    }

    float acc[2][8][4];
    #pragma unroll
    for (int a = 0; a < 2; a++)
        #pragma unroll
        for (int b = 0; b < 8; b++)
            #pragma unroll
            for (int c = 0; c < 4; c++) acc[a][b][c] = 0.0f;

    CP_ASYNC_WAIT0();
    __syncthreads();   // W2 + sp16 + biases visible; only barrier before loop

    // ============ layer2 mainloop: 8 chunks of k=32, barrier-free ===========
    #pragma unroll
    for (int c = 0; c < 8; ++c) {
        uint32_t af[2][2][4];
        #pragma unroll
        for (int ks = 0; ks < 2; ++ks) {
            const uint32_t spA = *(const uint32_t*)(smem + SM_SP16 + c * 64 + ks * 32 + (lane & 3) * 4);
            const uint32_t spB = *(const uint32_t*)(smem + SM_SP16 + c * 64 + ks * 32 + (lane & 3) * 4 + 16);
            #pragma unroll
            for (int tm = 0; tm < 2; ++tm) {
                af[tm][ks][0] = hadd2_relu(aq[tm][ks].x, spA);
                af[tm][ks][1] = hadd2_relu(aq[tm][ks].y, spA);
                af[tm][ks][2] = hadd2_relu(aq[tm][ks].z, spB);
                af[tm][ks][3] = hadd2_relu(aq[tm][ks].w, spB);
            }
        }
        if (c < 7) {
            #pragma unroll
            for (int ks = 0; ks < 2; ++ks) {
                aq[0][ks] = qbase0[((c + 1) * 2 + ks) * 2048];
                aq[1][ks] = qbase1[((c + 1) * 2 + ks) * 2048];
            }
        }
        #pragma unroll
        for (int ks = 0; ks < 2; ++ks) {
            #pragma unroll
            for (int tp = 0; tp < 4; ++tp) {
                uint32_t bh[4];
                const int nrow = wn * 64 + tp * 16 + (lane & 7) + 8 * (lane >> 4);
                const int kcol = c * 32 + ks * 16 + 8 * ((lane >> 3) & 1);
                ldsm4(bh, sb + SM_W2 + nrow * 528 + kcol * 2);
                #pragma unroll
                for (int tm = 0; tm < 2; ++tm) {
                    mma_f16(acc[tm][2*tp    ], af[tm][ks], &bh[0]);
                    mma_f16(acc[tm][2*tp + 1], af[tm][ks], &bh[2]);
                }
            }
        }
    }
    __syncthreads();   // all W2 reads done CTA-wide; W2 region reusable

    // stage W3^T into W2's region via cp.async (overlaps epilogue below)
    {
        const char* srcH = (const char*)g_W3TB;
        #pragma unroll
        for (int i = 0; i < 5; ++i) {
            const int t = tid + 256 * i;
            if (t < 1088) cp_async16(sb + SM_W3 + t * 16, srcH + t * 16);
        }
        CP_ASYNC_COMMIT();
    }
    // layer2 epilogue: bias+relu -> fp16 -> h2[m][k]
    {
        uint32_t* hh = reinterpret_cast<uint32_t*>(smem + SM_H2);
        #pragma unroll
        for (int tm = 0; tm < 2; ++tm) {
            #pragma unroll
            for (int tn = 0; tn < 8; ++tn) {
                const int n = wn * 64 + tn * 8 + (lane & 3) * 2;
                const int m = wm * 32 + tm * 16 + (lane >> 2);
                const float bn0 = b2s[n], bn1 = b2s[n + 1];
                #pragma unroll
                for (int rr = 0; rr < 2; ++rr) {
                    const float x0 = frelu(acc[tm][tn][2*rr    ] + bn0);
                    const float x1 = frelu(acc[tm][tn][2*rr + 1] + bn1);
                    hh[(m + 8*rr) * 68 + (n >> 1)] =
                        pack2h(__float2half_rn(x0), __float2half_rn(x1));
                }
            }
        }
    }
    CP_ASYNC_WAIT0();
    __syncthreads();

    // =================== layer3: h2[128x128] @ W3[128x64] ===================
    float acc3[2][4][4];
    #pragma unroll
    for (int a = 0; a < 2; a++)
        #pragma unroll
        for (int b = 0; b < 4; b++)
            #pragma unroll
            for (int c = 0; c < 4; c++) acc3[a][b][c] = 0.0f;

    #pragma unroll
    for (int ks = 0; ks < 8; ++ks) {
        uint32_t afr[2][4];
        #pragma unroll
        for (int tm = 0; tm < 2; ++tm) {
            const int mrow = wm * 32 + tm * 16 + (lane & 7) + 8 * ((lane >> 3) & 1);
            const int kcol = ks * 16 + 8 * (lane >> 4);
            ldsm4(afr[tm], sb + SM_H2 + mrow * 272 + kcol * 2);
        }
        #pragma unroll
        for (int tp = 0; tp < 2; ++tp) {
            uint32_t bh[4];
            const int nrow = wn * 32 + tp * 16 + (lane & 7) + 8 * (lane >> 4);
            const int kcol = ks * 16 + 8 * ((lane >> 3) & 1);
            ldsm4(bh, sb + SM_W3 + nrow * 272 + kcol * 2);
            #pragma unroll
            for (int tm = 0; tm < 2; ++tm) {
                mma_f16(acc3[tm][2*tp    ], afr[tm], &bh[0]);
                mma_f16(acc3[tm][2*tp + 1], afr[tm], &bh[2]);
            }
        }
    }

    // ============== layer3 epilogue + layer4 (registers + shfl) =============
    float part[4] = {0.0f, 0.0f, 0.0f, 0.0f};
    #pragma unroll
    for (int tn = 0; tn < 4; ++tn) {
        const int n = wn * 32 + tn * 8 + (lane & 3) * 2;
        const float bn0 = b3s[n], bn1 = b3s[n + 1];
        const float w0 = W4s[n],  w1 = W4s[n + 1];
        #pragma unroll
        for (int tm = 0; tm < 2; ++tm) {
            #pragma unroll
            for (int rr = 0; rr < 2; ++rr) {
                part[tm*2 + rr] += frelu(acc3[tm][tn][2*rr    ] + bn0) * w0
                                 + frelu(acc3[tm][tn][2*rr + 1] + bn1) * w1;
            }
        }
    }
    #pragma unroll
    for (int i = 0; i < 4; ++i) {
        part[i] += __shfl_xor_sync(0xffffffffu, part[i], 1);
        part[i] += __shfl_xor_sync(0xffffffffu, part[i], 2);
    }
    if ((lane & 3) == 0) {
        #pragma unroll
        for (int tm = 0; tm < 2; ++tm)
            #pragma unroll
            for (int rr = 0; rr < 2; ++rr) {
                const int m = wm * 32 + tm * 16 + rr * 8 + (lane >> 2);
                red[wn * 128 + m] = part[tm*2 + rr];
            }
    }
    __syncthreads();
    if (tid < 128) {
        const float v = red[tid] + red[128 + tid] + b4[0];
        out[(q0 + tid) * NS + s_idx] = 1.0f / (1.0f + expf(-v));
    }
}

// ---------------------------------------------------------------------------
extern "C" void kernel_launch(void* const* d_in, const int* in_sizes, int n_in,
                              void* d_out, int out_size)
{
    const float* qf = (const float*)d_in[0];
    const float* sf = (const float*)d_in[1];
    // d_in[2] = support_y (unused)
    const float* W1 = (const float*)d_in[3];
    const float* b1 = (const float*)d_in[4];
    const float* W2 = (const float*)d_in[5];
    const float* b2 = (const float*)d_in[6];
    const float* W3 = (const float*)d_in[7];
    const float* b3 = (const float*)d_in[8];
    const float* W4 = (const float*)d_in[9];
    const float* b4 = (const float*)d_in[10];
    float* out = (float*)d_out;

    cudaFuncSetAttribute(relation_mma_kernel,
                         cudaFuncAttributeMaxDynamicSharedMemorySize, SMEM_TOTAL);
    cudaFuncSetAttribute(precompute_mma_kernel,
                         cudaFuncAttributeMaxDynamicSharedMemorySize, PRE_SMEM_TOTAL);

    precompute_mma_kernel<<<dim3(15, 2), 256, PRE_SMEM_TOTAL>>>(qf, sf, b1, W1, W2, W3);
    relation_mma_kernel<<<dim3(NS, NQ / TM), 256, SMEM_TOTAL>>>(b2, b3, W4, b4, out);
}

// round 16
// speedup vs baseline: 1.1758x; 1.0254x over previous
#include <cuda_runtime.h>
#include <cuda_fp16.h>
#include <math.h>
#include <stdint.h>

#define NQ 1024
#define NS 256
#define E  256
#define H1 256
#define H2 128
#define H3 64
#define TM 128          // query rows per CTA

// ---------------- warp-MMA helpers (plain sm_80+ PTX) -----------------------
__device__ __forceinline__ uint32_t smem_to_u32(const void* p) {
    uint32_t a;
    asm("{ .reg .u64 t; cvta.to.shared.u64 t, %1; cvt.u32.u64 %0, t; }" : "=r"(a) : "l"(p));
    return a;
}
__device__ __forceinline__ void ldsm4(uint32_t* r, uint32_t addr) {
    asm volatile("ldmatrix.sync.aligned.m8n8.x4.shared.b16 {%0,%1,%2,%3}, [%4];"
                 : "=r"(r[0]), "=r"(r[1]), "=r"(r[2]), "=r"(r[3]) : "r"(addr));
}
__device__ __forceinline__ void mma_f16(float* d, const uint32_t* a, const uint32_t* b) {
    asm volatile("mma.sync.aligned.m16n8k16.row.col.f32.f16.f16.f32 "
                 "{%0,%1,%2,%3}, {%4,%5,%6,%7}, {%8,%9}, {%0,%1,%2,%3};"
                 : "+f"(d[0]), "+f"(d[1]), "+f"(d[2]), "+f"(d[3])
                 : "r"(a[0]), "r"(a[1]), "r"(a[2]), "r"(a[3]), "r"(b[0]), "r"(b[1]));
}
__device__ __forceinline__ void cp_async16(uint32_t dst_smem, const void* src) {
    asm volatile("cp.async.cg.shared.global [%0], [%1], 16;"
                 :: "r"(dst_smem), "l"(src));
}
#define CP_ASYNC_COMMIT() asm volatile("cp.async.commit_group;" ::: "memory")
#define CP_ASYNC_WAIT0()  asm volatile("cp.async.wait_group 0;" ::: "memory")

__device__ __forceinline__ void split_f16(float x, __half& hi, __half& lo) {
    hi = __float2half_rn(x);
    lo = __float2half_rn(x - __half2float(hi));
}
__device__ __forceinline__ uint32_t pack2h(__half a, __half b) {
    __half2 t; t.x = a; t.y = b;
    return *reinterpret_cast<uint32_t*>(&t);
}
// relu(a + b) in ONE instruction: HFMA2.RELU (a*1 + b, exact, fused relu)
__device__ __forceinline__ uint32_t hadd2_relu(uint32_t a, uint32_t b) {
    const __half2 one = __half2(__half(1.0f), __half(1.0f));
    __half2 r = __hfma2_relu(*reinterpret_cast<__half2*>(&a), one,
                             *reinterpret_cast<__half2*>(&b));
    return *reinterpret_cast<uint32_t*>(&r);
}
__device__ __forceinline__ float frelu(float x) { return fmaxf(x, 0.0f); }

// ---------------- global scratch (static) -----------------------------------
__device__ uint4  g_QpF[16 * 64 * 32];        // [K16][M16][lane] fp16 A-fragments
__device__ float  g_Sp [NS * H1];             // [s][k] (+b1)
__device__ __half g_W2TB[128 * 264];          // [n][264k] fp16, k<256 data
__device__ __half g_W3TB[8704];               // [n*136+k] fp16

// ---------------- main-kernel smem layout (bytes) ----------------------------
#define SM_W2   0         // whole W2^T [128n][264k] fp16 = 67584
#define SM_W3   0         // phase B: W3^T [64n][136k] = 17408 (aliases SM_W2)
#define SM_H2   67584     // h2 fp16 [128m][136k] = 34816 (ends 102400)
#define SM_SP16 102400    // 256 fp16 = 512
#define SM_B2S  102912    // 128 f32
#define SM_B3S  103424    // 64 f32
#define SM_W4S  103680    // 64 f32
#define SM_RED  103936    // 2*128 f32 = 1024
#define SMEM_TOTAL 104960

// ---------------- precompute-kernel smem layout ------------------------------
#define PSM_A  0          // feat fp16 [128m][264k] = 67584
#define PSM_B  67584      // W1 stage: 2 x (hi 10240 + lo 10240) = 40960
#define PB_STRIDE 20480
#define PRE_SMEM_TOTAL 108544

// ---------------------------------------------------------------------------
// Precompute via mma: Qp -> g_QpF fragments; Sp -> g_Sp.
// R15: 512 threads (16 warps: wm 0..7 x wn 0..1) for 4 warps/SMSP latency
// hiding; W1 register-prefetched one chunk ahead (wreg). One sync per chunk.
// mb 0..9: GEMM CTAs. mb 10..14: W2/W3 fp16 conversion (runs concurrently).
// ---------------------------------------------------------------------------
__global__ void __launch_bounds__(512)
precompute_mma_kernel(const float* __restrict__ qf,
                      const float* __restrict__ sf,
                      const float* __restrict__ b1,
                      const float* __restrict__ W1,
                      const float* __restrict__ W2,
                      const float* __restrict__ W3)
{
    const int mb = blockIdx.x;         // 0..14
    const int nb = blockIdx.y;         // 0..1

    if (mb >= 10) {
        const int cid = (mb - 10) * 2 + nb;     // 0..9
        for (int e = cid * 512 + threadIdx.x; e < 33792 + 8704; e += 5120) {
            if (e < 33792) {
                const int n = e / 264, k = e % 264;
                const float w = (k < 256) ? W2[k * H2 + n] : 0.0f;
                g_W2TB[e] = __float2half_rn(w);
            } else {
                const int t = e - 33792;
                const int n = t / 136, k = t % 136;
                const float w = (k < 128) ? W3[k * H3 + n] : 0.0f;
                g_W3TB[t] = __float2half_rn(w);
            }
        }
        return;
    }

    extern __shared__ char smem[];
    const uint32_t sb = smem_to_u32(smem);
    const int tid  = threadIdx.x;      // 0..511
    const int lane = tid & 31;
    const int wid  = tid >> 5;         // 0..15
    const int wm   = wid & 7;          // 8 warps along M (16 rows each)
    const int wn   = wid >> 3;         // 2 warps along N (64 cols each)
    const bool isQ = (mb < 8);
    const float* feat = isQ ? (qf + mb * 128 * E) : (sf + (mb - 8) * 128 * E);
    const int hf = isQ ? 0 : 1;

    // W1 conversion ownership: n = tid&127, kk group of 8 = (tid>>7)*8
    const int cv_n   = tid & 127;
    const int cv_kkb = (tid >> 7) * 8;      // 0,8,16,24
    const float* W1base = W1 + (hf * 256) * H1 + nb * 128 + cv_n;

    // ---- register prefetch: W1 chunk 0 ----
    float wreg[8];
    #pragma unroll
    for (int j = 0; j < 8; ++j)
        wreg[j] = W1base[(cv_kkb + j) * H1];

    // ---- stage A: feat[128][256] f32 -> fp16 smem [128][264] ----
    {
        const int row = tid >> 2, part = tid & 3;   // 4 threads per row
        const float4* src = reinterpret_cast<const float4*>(feat + row * E);
        uint32_t* dst = reinterpret_cast<uint32_t*>(smem + PSM_A);
        #pragma unroll 4
        for (int j = 0; j < 16; ++j) {
            const float4 v = src[part * 16 + j];
            const int u = row * 132 + (part * 16 + j) * 2;
            dst[u]     = pack2h(__float2half_rn(v.x), __float2half_rn(v.y));
            dst[u + 1] = pack2h(__float2half_rn(v.z), __float2half_rn(v.w));
        }
    }

    float acc[8][4];
    #pragma unroll
    for (int b = 0; b < 8; b++)
        #pragma unroll
        for (int c = 0; c < 4; c++) acc[b][c] = 0.0f;

    for (int c = 0; c < 8; ++c) {
        const int st = c & 1;
        // convert wreg (chunk c) -> buf[st]
        {
            uint32_t* bufH = reinterpret_cast<uint32_t*>(smem + PSM_B + st * PB_STRIDE);
            uint32_t* bufL = reinterpret_cast<uint32_t*>(smem + PSM_B + st * PB_STRIDE + 10240);
            #pragma unroll
            for (int j = 0; j < 4; ++j) {
                const int kk = cv_kkb + 2 * j;
                __half h0, l0, h1, l1;
                split_f16(wreg[2*j    ], h0, l0);
                split_f16(wreg[2*j + 1], h1, l1);
                bufH[cv_n * 20 + (kk >> 1)] = pack2h(h0, h1);
                bufL[cv_n * 20 + (kk >> 1)] = pack2h(l0, l1);
            }
        }
        if (c < 7) {   // prefetch W1 chunk c+1 (latency spans the mma phase)
            #pragma unroll
            for (int j = 0; j < 8; ++j)
                wreg[j] = W1base[((c + 1) * 32 + cv_kkb + j) * H1];
        }
        __syncthreads();   // buf[st] (+ stage A on c=0) visible

        #pragma unroll
        for (int ks = 0; ks < 2; ++ks) {
            uint32_t afr[4];
            const int mrow = wm * 16 + (lane & 7) + 8 * ((lane >> 3) & 1);
            const int kcol = c * 32 + ks * 16 + 8 * (lane >> 4);
            ldsm4(afr, sb + PSM_A + mrow * 528 + kcol * 2);
            #pragma unroll
            for (int tp = 0; tp < 4; ++tp) {
                uint32_t bh[4], bl[4];
                const int nrow = wn * 64 + tp * 16 + (lane & 7) + 8 * (lane >> 4);
                const int kcol2 = ks * 16 + 8 * ((lane >> 3) & 1);
                const uint32_t baddr = sb + PSM_B + st * PB_STRIDE + nrow * 80 + kcol2 * 2;
                ldsm4(bh, baddr);
                ldsm4(bl, baddr + 10240);
                mma_f16(acc[2*tp    ], afr, &bh[0]);
                mma_f16(acc[2*tp    ], afr, &bl[0]);
                mma_f16(acc[2*tp + 1], afr, &bh[2]);
                mma_f16(acc[2*tp + 1], afr, &bl[2]);
            }
        }
        // next iteration's STS targets buf[st^1]; its readers (mma of chunk
        // c-1) completed before this chunk's sync -> one sync per chunk safe.
    }

    // ---- epilogue ----
    if (isQ) {
        #pragma unroll
        for (int tnp = 0; tnp < 4; ++tnp) {
            const int K16 = nb * 8 + wn * 4 + tnp;
            const int M16 = mb * 8 + wm;
            uint4 v;
            v.x = pack2h(__float2half_rn(acc[2*tnp][0]),
                         __float2half_rn(acc[2*tnp][1]));
            v.y = pack2h(__float2half_rn(acc[2*tnp][2]),
                         __float2half_rn(acc[2*tnp][3]));
            v.z = pack2h(__float2half_rn(acc[2*tnp+1][0]),
                         __float2half_rn(acc[2*tnp+1][1]));
            v.w = pack2h(__float2half_rn(acc[2*tnp+1][2]),
                         __float2half_rn(acc[2*tnp+1][3]));
            g_QpF[(K16 * 64 + M16) * 32 + lane] = v;
        }
    } else {
        const int s0 = (mb - 8) * 128;
        #pragma unroll
        for (int tn = 0; tn < 8; ++tn) {
            const int n = nb * 128 + wn * 64 + tn * 8 + (lane & 3) * 2;
            const float bb0 = b1[n], bb1 = b1[n + 1];
            #pragma unroll
            for (int rr = 0; rr < 2; ++rr) {
                const int m = wm * 16 + rr * 8 + (lane >> 2);
                g_Sp[(s0 + m) * H1 + n]     = acc[tn][2*rr]     + bb0;
                g_Sp[(s0 + m) * H1 + n + 1] = acc[tn][2*rr + 1] + bb1;
            }
        }
    }
}

// ---------------------------------------------------------------------------
// Fused MLP (R15 winner, unchanged): whole W2 resident; barrier-free layer2
// mainloop; HFMA2.RELU A-fragment build; immediate-offset aq prefetch.
// ---------------------------------------------------------------------------
__global__ void __launch_bounds__(256, 2)
relation_mma_kernel(const float* __restrict__ b2,
                    const float* __restrict__ b3,
                    const float* __restrict__ W4,
                    const float* __restrict__ b4,
                    float* __restrict__ out)
{
    extern __shared__ char smem[];
    const uint32_t sb = smem_to_u32(smem);
    const int tid  = threadIdx.x;
    const int lane = tid & 31;
    const int wid  = tid >> 5;
    const int wm   = wid & 3;
    const int wn   = wid >> 2;
    const int s_idx = blockIdx.x;
    const int q0    = blockIdx.y * TM;
    const int M16b  = blockIdx.y * 8 + wm * 2;

    float* b2s = (float*)(smem + SM_B2S);
    float* b3s = (float*)(smem + SM_B3S);
    float* W4s = (float*)(smem + SM_W4S);
    float* red = (float*)(smem + SM_RED);
    __half* sp16 = (__half*)(smem + SM_SP16);

    sp16[tid] = __float2half_rn(g_Sp[s_idx * H1 + tid]);
    if (tid < H2) b2s[tid] = b2[tid];
    if (tid < H3) { b3s[tid] = b3[tid]; W4s[tid] = W4[tid]; }

    // ---- prologue: cp.async the WHOLE W2 (67584 B = 4224 x 16B) ----
    {
        const char* src = (const char*)g_W2TB;
        #pragma unroll
        for (int i = 0; i < 17; ++i) {
            const int t = tid + 256 * i;
            if (t < 4224) cp_async16(sb + SM_W2 + t * 16, src + t * 16);
        }
        CP_ASYNC_COMMIT();
    }
    const uint4* qbase0 = &g_QpF[(M16b    ) * 32 + lane];
    const uint4* qbase1 = &g_QpF[(M16b + 1) * 32 + lane];
    uint4 aq[2][2];
    #pragma unroll
    for (int ks = 0; ks < 2; ++ks) {
        aq[0][ks] = qbase0[ks * 2048];
        aq[1][ks] = qbase1[ks * 2048];
    }

    float acc[2][8][4];
    #pragma unroll
    for (int a = 0; a < 2; a++)
        #pragma unroll
        for (int b = 0; b < 8; b++)
            #pragma unroll
            for (int c = 0; c < 4; c++) acc[a][b][c] = 0.0f;

    CP_ASYNC_WAIT0();
    __syncthreads();   // W2 + sp16 + biases visible; only barrier before loop

    // ============ layer2 mainloop: 8 chunks of k=32, barrier-free ===========
    #pragma unroll
    for (int c = 0; c < 8; ++c) {
        uint32_t af[2][2][4];
        #pragma unroll
        for (int ks = 0; ks < 2; ++ks) {
            const uint32_t spA = *(const uint32_t*)(smem + SM_SP16 + c * 64 + ks * 32 + (lane & 3) * 4);
            const uint32_t spB = *(const uint32_t*)(smem + SM_SP16 + c * 64 + ks * 32 + (lane & 3) * 4 + 16);
            #pragma unroll
            for (int tm = 0; tm < 2; ++tm) {
                af[tm][ks][0] = hadd2_relu(aq[tm][ks].x, spA);
                af[tm][ks][1] = hadd2_relu(aq[tm][ks].y, spA);
                af[tm][ks][2] = hadd2_relu(aq[tm][ks].z, spB);
                af[tm][ks][3] = hadd2_relu(aq[tm][ks].w, spB);
            }
        }
        if (c < 7) {
            #pragma unroll
            for (int ks = 0; ks < 2; ++ks) {
                aq[0][ks] = qbase0[((c + 1) * 2 + ks) * 2048];
                aq[1][ks] = qbase1[((c + 1) * 2 + ks) * 2048];
            }
        }
        #pragma unroll
        for (int ks = 0; ks < 2; ++ks) {
            #pragma unroll
            for (int tp = 0; tp < 4; ++tp) {
                uint32_t bh[4];
                const int nrow = wn * 64 + tp * 16 + (lane & 7) + 8 * (lane >> 4);
                const int kcol = c * 32 + ks * 16 + 8 * ((lane >> 3) & 1);
                ldsm4(bh, sb + SM_W2 + nrow * 528 + kcol * 2);
                #pragma unroll
                for (int tm = 0; tm < 2; ++tm) {
                    mma_f16(acc[tm][2*tp    ], af[tm][ks], &bh[0]);
                    mma_f16(acc[tm][2*tp + 1], af[tm][ks], &bh[2]);
                }
            }
        }
    }
    __syncthreads();   // all W2 reads done CTA-wide; W2 region reusable

    // stage W3^T into W2's region via cp.async (overlaps epilogue below)
    {
        const char* srcH = (const char*)g_W3TB;
        #pragma unroll
        for (int i = 0; i < 5; ++i) {
            const int t = tid + 256 * i;
            if (t < 1088) cp_async16(sb + SM_W3 + t * 16, srcH + t * 16);
        }
        CP_ASYNC_COMMIT();
    }
    // layer2 epilogue: bias+relu -> fp16 -> h2[m][k]
    {
        uint32_t* hh = reinterpret_cast<uint32_t*>(smem + SM_H2);
        #pragma unroll
        for (int tm = 0; tm < 2; ++tm) {
            #pragma unroll
            for (int tn = 0; tn < 8; ++tn) {
                const int n = wn * 64 + tn * 8 + (lane & 3) * 2;
                const int m = wm * 32 + tm * 16 + (lane >> 2);
                const float bn0 = b2s[n], bn1 = b2s[n + 1];
                #pragma unroll
                for (int rr = 0; rr < 2; ++rr) {
                    const float x0 = frelu(acc[tm][tn][2*rr    ] + bn0);
                    const float x1 = frelu(acc[tm][tn][2*rr + 1] + bn1);
                    hh[(m + 8*rr) * 68 + (n >> 1)] =
                        pack2h(__float2half_rn(x0), __float2half_rn(x1));
                }
            }
        }
    }
    CP_ASYNC_WAIT0();
    __syncthreads();

    // =================== layer3: h2[128x128] @ W3[128x64] ===================
    float acc3[2][4][4];
    #pragma unroll
    for (int a = 0; a < 2; a++)
        #pragma unroll
        for (int b = 0; b < 4; b++)
            #pragma unroll
            for (int c = 0; c < 4; c++) acc3[a][b][c] = 0.0f;

    #pragma unroll
    for (int ks = 0; ks < 8; ++ks) {
        uint32_t afr[2][4];
        #pragma unroll
        for (int tm = 0; tm < 2; ++tm) {
            const int mrow = wm * 32 + tm * 16 + (lane & 7) + 8 * ((lane >> 3) & 1);
            const int kcol = ks * 16 + 8 * (lane >> 4);
            ldsm4(afr[tm], sb + SM_H2 + mrow * 272 + kcol * 2);
        }
        #pragma unroll
        for (int tp = 0; tp < 2; ++tp) {
            uint32_t bh[4];
            const int nrow = wn * 32 + tp * 16 + (lane & 7) + 8 * (lane >> 4);
            const int kcol = ks * 16 + 8 * ((lane >> 3) & 1);
            ldsm4(bh, sb + SM_W3 + nrow * 272 + kcol * 2);
            #pragma unroll
            for (int tm = 0; tm < 2; ++tm) {
                mma_f16(acc3[tm][2*tp    ], afr[tm], &bh[0]);
                mma_f16(acc3[tm][2*tp + 1], afr[tm], &bh[2]);
            }
        }
    }

    // ============== layer3 epilogue + layer4 (registers + shfl) =============
    float part[4] = {0.0f, 0.0f, 0.0f, 0.0f};
    #pragma unroll
    for (int tn = 0; tn < 4; ++tn) {
        const int n = wn * 32 + tn * 8 + (lane & 3) * 2;
        const float bn0 = b3s[n], bn1 = b3s[n + 1];
        const float w0 = W4s[n],  w1 = W4s[n + 1];
        #pragma unroll
        for (int tm = 0; tm < 2; ++tm) {
            #pragma unroll
            for (int rr = 0; rr < 2; ++rr) {
                part[tm*2 + rr] += frelu(acc3[tm][tn][2*rr    ] + bn0) * w0
                                 + frelu(acc3[tm][tn][2*rr + 1] + bn1) * w1;
            }
        }
    }
    #pragma unroll
    for (int i = 0; i < 4; ++i) {
        part[i] += __shfl_xor_sync(0xffffffffu, part[i], 1);
        part[i] += __shfl_xor_sync(0xffffffffu, part[i], 2);
    }
    if ((lane & 3) == 0) {
        #pragma unroll
        for (int tm = 0; tm < 2; ++tm)
            #pragma unroll
            for (int rr = 0; rr < 2; ++rr) {
                const int m = wm * 32 + tm * 16 + rr * 8 + (lane >> 2);
                red[wn * 128 + m] = part[tm*2 + rr];
            }
    }
    __syncthreads();
    if (tid < 128) {
        const float v = red[tid] + red[128 + tid] + b4[0];
        out[(q0 + tid) * NS + s_idx] = 1.0f / (1.0f + expf(-v));
    }
}

// ---------------------------------------------------------------------------
extern "C" void kernel_launch(void* const* d_in, const int* in_sizes, int n_in,
                              void* d_out, int out_size)
{
    const float* qf = (const float*)d_in[0];
    const float* sf = (const float*)d_in[1];
    // d_in[2] = support_y (unused)
    const float* W1 = (const float*)d_in[3];
    const float* b1 = (const float*)d_in[4];
    const float* W2 = (const float*)d_in[5];
    const float* b2 = (const float*)d_in[6];
    const float* W3 = (const float*)d_in[7];
    const float* b3 = (const float*)d_in[8];
    const float* W4 = (const float*)d_in[9];
    const float* b4 = (const float*)d_in[10];
    float* out = (float*)d_out;

    cudaFuncSetAttribute(relation_mma_kernel,
                         cudaFuncAttributeMaxDynamicSharedMemorySize, SMEM_TOTAL);
    cudaFuncSetAttribute(precompute_mma_kernel,
                         cudaFuncAttributeMaxDynamicSharedMemorySize, PRE_SMEM_TOTAL);

    precompute_mma_kernel<<<dim3(15, 2), 512, PRE_SMEM_TOTAL>>>(qf, sf, b1, W1, W2, W3);
    relation_mma_kernel<<<dim3(NS, NQ / TM), 256, SMEM_TOTAL>>>(b2, b3, W4, b4, out);
}

// round 17
// speedup vs baseline: 1.3053x; 1.1101x over previous
#include <cuda_runtime.h>
#include <cuda_fp16.h>
#include <math.h>
#include <stdint.h>

#define NQ 1024
#define NS 256
#define E  256
#define H1 256
#define H2 128
#define H3 64
#define TM 128          // query rows per CTA (main kernel)

// ---------------- warp-MMA helpers (plain sm_80+ PTX) -----------------------
__device__ __forceinline__ uint32_t smem_to_u32(const void* p) {
    uint32_t a;
    asm("{ .reg .u64 t; cvta.to.shared.u64 t, %1; cvt.u32.u64 %0, t; }" : "=r"(a) : "l"(p));
    return a;
}
__device__ __forceinline__ void ldsm4(uint32_t* r, uint32_t addr) {
    asm volatile("ldmatrix.sync.aligned.m8n8.x4.shared.b16 {%0,%1,%2,%3}, [%4];"
                 : "=r"(r[0]), "=r"(r[1]), "=r"(r[2]), "=r"(r[3]) : "r"(addr));
}
__device__ __forceinline__ void mma_f16(float* d, const uint32_t* a, const uint32_t* b) {
    asm volatile("mma.sync.aligned.m16n8k16.row.col.f32.f16.f16.f32 "
                 "{%0,%1,%2,%3}, {%4,%5,%6,%7}, {%8,%9}, {%0,%1,%2,%3};"
                 : "+f"(d[0]), "+f"(d[1]), "+f"(d[2]), "+f"(d[3])
                 : "r"(a[0]), "r"(a[1]), "r"(a[2]), "r"(a[3]), "r"(b[0]), "r"(b[1]));
}
__device__ __forceinline__ void cp_async16(uint32_t dst_smem, const void* src) {
    asm volatile("cp.async.cg.shared.global [%0], [%1], 16;"
                 :: "r"(dst_smem), "l"(src));
}
#define CP_ASYNC_COMMIT() asm volatile("cp.async.commit_group;" ::: "memory")
#define CP_ASYNC_WAIT0()  asm volatile("cp.async.wait_group 0;" ::: "memory")

__device__ __forceinline__ void split_f16(float x, __half& hi, __half& lo) {
    hi = __float2half_rn(x);
    lo = __float2half_rn(x - __half2float(hi));
}
__device__ __forceinline__ uint32_t pack2h(__half a, __half b) {
    __half2 t; t.x = a; t.y = b;
    return *reinterpret_cast<uint32_t*>(&t);
}
// relu(a + b) in ONE instruction: HFMA2.RELU (a*1 + b, exact, fused relu)
__device__ __forceinline__ uint32_t hadd2_relu(uint32_t a, uint32_t b) {
    const __half2 one = __half2(__half(1.0f), __half(1.0f));
    __half2 r = __hfma2_relu(*reinterpret_cast<__half2*>(&a), one,
                             *reinterpret_cast<__half2*>(&b));
    return *reinterpret_cast<uint32_t*>(&r);
}
__device__ __forceinline__ float frelu(float x) { return fmaxf(x, 0.0f); }

// ---------------- global scratch (static) -----------------------------------
__device__ uint4  g_QpF[16 * 64 * 32];        // [K16][M16][lane] fp16 A-fragments
__device__ float  g_Sp [NS * H1];             // [s][k] (+b1)
__device__ __half g_W2TB[128 * 264];          // [n][264k] fp16, k<256 data
__device__ __half g_W3TB[8704];               // [n*136+k] fp16

// ---------------- main-kernel smem layout (bytes) ----------------------------
#define SM_W2   0         // whole W2^T [128n][264k] fp16 = 67584
#define SM_W3   0         // phase B: W3^T [64n][136k] = 17408 (aliases SM_W2)
#define SM_H2   67584     // h2 fp16 [128m][136k] = 34816 (ends 102400)
#define SM_SP16 102400    // 256 fp16 = 512
#define SM_B2S  102912    // 128 f32
#define SM_B3S  103424    // 64 f32
#define SM_W4S  103680    // 64 f32
#define SM_RED  103936    // 2*128 f32 = 1024
#define SMEM_TOTAL 104960

// ---------------- precompute-kernel smem layout (M=32 tiles) -----------------
#define PSM_A  0          // feat fp16 [32m][264k] = 16896
#define PSM_B  17408      // W1 stage: 2 x (hi 10240 + lo 10240) = 40960
#define PB_STRIDE 20480
#define PRE_SMEM_TOTAL 58368

// ---------------------------------------------------------------------------
// Precompute via mma: Qp -> g_QpF fragments; Sp -> g_Sp.
// R16: M-tile 32 rows -> 80 GEMM CTAs (4x SM coverage; was the 20-CTA
// utilization bound). 16 warps = wm{0,1} x wn[0,8). W1 converted inline,
// register-prefetched one chunk ahead. mb 40..44: W2/W3 conversion CTAs.
// ---------------------------------------------------------------------------
__global__ void __launch_bounds__(512)
precompute_mma_kernel(const float* __restrict__ qf,
                      const float* __restrict__ sf,
                      const float* __restrict__ b1,
                      const float* __restrict__ W1,
                      const float* __restrict__ W2,
                      const float* __restrict__ W3)
{
    const int mb = blockIdx.x;         // 0..44
    const int nb = blockIdx.y;         // 0..1

    if (mb >= 40) {
        const int cid = (mb - 40) * 2 + nb;     // 0..9
        for (int e = cid * 512 + threadIdx.x; e < 33792 + 8704; e += 5120) {
            if (e < 33792) {
                const int n = e / 264, k = e % 264;
                const float w = (k < 256) ? W2[k * H2 + n] : 0.0f;
                g_W2TB[e] = __float2half_rn(w);
            } else {
                const int t = e - 33792;
                const int n = t / 136, k = t % 136;
                const float w = (k < 128) ? W3[k * H3 + n] : 0.0f;
                g_W3TB[t] = __float2half_rn(w);
            }
        }
        return;
    }

    extern __shared__ char smem[];
    const uint32_t sb = smem_to_u32(smem);
    const int tid  = threadIdx.x;      // 0..511
    const int lane = tid & 31;
    const int wid  = tid >> 5;         // 0..15
    const int wm   = wid & 1;          // 2 m16 tiles
    const int wn   = wid >> 1;         // 8 warps x 16 n-cols
    const bool isQ = (mb < 32);
    const float* feat = isQ ? (qf + mb * 32 * E) : (sf + (mb - 32) * 32 * E);
    const int hf = isQ ? 0 : 1;

    // W1 conversion ownership: n = tid&127, kk group of 8 = (tid>>7)*8
    const int cv_n   = tid & 127;
    const int cv_kkb = (tid >> 7) * 8;      // 0,8,16,24
    const float* W1base = W1 + (hf * 256) * H1 + nb * 128 + cv_n;

    // ---- register prefetch: W1 chunk 0 ----
    float wreg[8];
    #pragma unroll
    for (int j = 0; j < 8; ++j)
        wreg[j] = W1base[(cv_kkb + j) * H1];

    // ---- stage A: feat[32][256] f32 -> fp16 smem [32][264] ----
    {
        const int row = tid >> 4, part = tid & 15;   // 16 threads per row
        const float4* src = reinterpret_cast<const float4*>(feat + row * E);
        uint32_t* dst = reinterpret_cast<uint32_t*>(smem + PSM_A);
        #pragma unroll
        for (int j = 0; j < 4; ++j) {
            const float4 v = src[part * 4 + j];
            const int u = row * 132 + (part * 4 + j) * 2;
            dst[u]     = pack2h(__float2half_rn(v.x), __float2half_rn(v.y));
            dst[u + 1] = pack2h(__float2half_rn(v.z), __float2half_rn(v.w));
        }
    }

    float acc[2][4];   // [n8 tile][quad]
    #pragma unroll
    for (int b = 0; b < 2; b++)
        #pragma unroll
        for (int c = 0; c < 4; c++) acc[b][c] = 0.0f;

    for (int c = 0; c < 8; ++c) {
        const int st = c & 1;
        // convert wreg (chunk c) -> buf[st]
        {
            uint32_t* bufH = reinterpret_cast<uint32_t*>(smem + PSM_B + st * PB_STRIDE);
            uint32_t* bufL = reinterpret_cast<uint32_t*>(smem + PSM_B + st * PB_STRIDE + 10240);
            #pragma unroll
            for (int j = 0; j < 4; ++j) {
                const int kk = cv_kkb + 2 * j;
                __half h0, l0, h1, l1;
                split_f16(wreg[2*j    ], h0, l0);
                split_f16(wreg[2*j + 1], h1, l1);
                bufH[cv_n * 20 + (kk >> 1)] = pack2h(h0, h1);
                bufL[cv_n * 20 + (kk >> 1)] = pack2h(l0, l1);
            }
        }
        if (c < 7) {   // prefetch W1 chunk c+1 (latency spans the mma phase)
            #pragma unroll
            for (int j = 0; j < 8; ++j)
                wreg[j] = W1base[((c + 1) * 32 + cv_kkb + j) * H1];
        }
        __syncthreads();   // buf[st] (+ stage A on c=0) visible

        #pragma unroll
        for (int ks = 0; ks < 2; ++ks) {
            uint32_t afr[4];
            const int mrow = wm * 16 + (lane & 7) + 8 * ((lane >> 3) & 1);
            const int kcol = c * 32 + ks * 16 + 8 * (lane >> 4);
            ldsm4(afr, sb + PSM_A + mrow * 528 + kcol * 2);
            uint32_t bh[4], bl[4];
            const int nrow = wn * 16 + (lane & 7) + 8 * (lane >> 4);
            const int kcol2 = ks * 16 + 8 * ((lane >> 3) & 1);
            const uint32_t baddr = sb + PSM_B + st * PB_STRIDE + nrow * 80 + kcol2 * 2;
            ldsm4(bh, baddr);
            ldsm4(bl, baddr + 10240);
            mma_f16(acc[0], afr, &bh[0]);
            mma_f16(acc[0], afr, &bl[0]);
            mma_f16(acc[1], afr, &bh[2]);
            mma_f16(acc[1], afr, &bl[2]);
        }
        // next iteration's STS targets buf[st^1]; its readers completed
        // before this chunk's sync -> one sync per chunk safe.
    }

    // ---- epilogue ----
    if (isQ) {
        const int K16 = nb * 8 + wn;
        const int M16 = mb * 2 + wm;
        uint4 v;
        v.x = pack2h(__float2half_rn(acc[0][0]), __float2half_rn(acc[0][1]));
        v.y = pack2h(__float2half_rn(acc[0][2]), __float2half_rn(acc[0][3]));
        v.z = pack2h(__float2half_rn(acc[1][0]), __float2half_rn(acc[1][1]));
        v.w = pack2h(__float2half_rn(acc[1][2]), __float2half_rn(acc[1][3]));
        g_QpF[(K16 * 64 + M16) * 32 + lane] = v;
    } else {
        const int s0 = (mb - 32) * 32;
        #pragma unroll
        for (int tn = 0; tn < 2; ++tn) {
            const int n = nb * 128 + wn * 16 + tn * 8 + (lane & 3) * 2;
            const float bb0 = b1[n], bb1 = b1[n + 1];
            #pragma unroll
            for (int rr = 0; rr < 2; ++rr) {
                const int m = wm * 16 + rr * 8 + (lane >> 2);
                g_Sp[(s0 + m) * H1 + n]     = acc[tn][2*rr]     + bb0;
                g_Sp[(s0 + m) * H1 + n + 1] = acc[tn][2*rr + 1] + bb1;
            }
        }
    }
}

// ---------------------------------------------------------------------------
// Fused MLP (R15 winner, unchanged): whole W2 resident; barrier-free layer2
// mainloop; HFMA2.RELU A-fragment build; immediate-offset aq prefetch.
// ---------------------------------------------------------------------------
__global__ void __launch_bounds__(256, 2)
relation_mma_kernel(const float* __restrict__ b2,
                    const float* __restrict__ b3,
                    const float* __restrict__ W4,
                    const float* __restrict__ b4,
                    float* __restrict__ out)
{
    extern __shared__ char smem[];
    const uint32_t sb = smem_to_u32(smem);
    const int tid  = threadIdx.x;
    const int lane = tid & 31;
    const int wid  = tid >> 5;
    const int wm   = wid & 3;
    const int wn   = wid >> 2;
    const int s_idx = blockIdx.x;
    const int q0    = blockIdx.y * TM;
    const int M16b  = blockIdx.y * 8 + wm * 2;

    float* b2s = (float*)(smem + SM_B2S);
    float* b3s = (float*)(smem + SM_B3S);
    float* W4s = (float*)(smem + SM_W4S);
    float* red = (float*)(smem + SM_RED);
    __half* sp16 = (__half*)(smem + SM_SP16);

    sp16[tid] = __float2half_rn(g_Sp[s_idx * H1 + tid]);
    if (tid < H2) b2s[tid] = b2[tid];
    if (tid < H3) { b3s[tid] = b3[tid]; W4s[tid] = W4[tid]; }

    // ---- prologue: cp.async the WHOLE W2 (67584 B = 4224 x 16B) ----
    {
        const char* src = (const char*)g_W2TB;
        #pragma unroll
        for (int i = 0; i < 17; ++i) {
            const int t = tid + 256 * i;
            if (t < 4224) cp_async16(sb + SM_W2 + t * 16, src + t * 16);
        }
        CP_ASYNC_COMMIT();
    }
    const uint4* qbase0 = &g_QpF[(M16b    ) * 32 + lane];
    const uint4* qbase1 = &g_QpF[(M16b + 1) * 32 + lane];
    uint4 aq[2][2];
    #pragma unroll
    for (int ks = 0; ks < 2; ++ks) {
        aq[0][ks] = qbase0[ks * 2048];
        aq[1][ks] = qbase1[ks * 2048];
    }

    float acc[2][8][4];
    #pragma unroll
    for (int a = 0; a < 2; a++)
        #pragma unroll
        for (int b = 0; b < 8; b++)
            #pragma unroll
            for (int c = 0; c < 4; c++) acc[a][b][c] = 0.0f;

    CP_ASYNC_WAIT0();
    __syncthreads();   // W2 + sp16 + biases visible; only barrier before loop

    // ============ layer2 mainloop: 8 chunks of k=32, barrier-free ===========
    #pragma unroll
    for (int c = 0; c < 8; ++c) {
        uint32_t af[2][2][4];
        #pragma unroll
        for (int ks = 0; ks < 2; ++ks) {
            const uint32_t spA = *(const uint32_t*)(smem + SM_SP16 + c * 64 + ks * 32 + (lane & 3) * 4);
            const uint32_t spB = *(const uint32_t*)(smem + SM_SP16 + c * 64 + ks * 32 + (lane & 3) * 4 + 16);
            #pragma unroll
            for (int tm = 0; tm < 2; ++tm) {
                af[tm][ks][0] = hadd2_relu(aq[tm][ks].x, spA);
                af[tm][ks][1] = hadd2_relu(aq[tm][ks].y, spA);
                af[tm][ks][2] = hadd2_relu(aq[tm][ks].z, spB);
                af[tm][ks][3] = hadd2_relu(aq[tm][ks].w, spB);
            }
        }
        if (c < 7) {
            #pragma unroll
            for (int ks = 0; ks < 2; ++ks) {
                aq[0][ks] = qbase0[((c + 1) * 2 + ks) * 2048];
                aq[1][ks] = qbase1[((c + 1) * 2 + ks) * 2048];
            }
        }
        #pragma unroll
        for (int ks = 0; ks < 2; ++ks) {
            #pragma unroll
            for (int tp = 0; tp < 4; ++tp) {
                uint32_t bh[4];
                const int nrow = wn * 64 + tp * 16 + (lane & 7) + 8 * (lane >> 4);
                const int kcol = c * 32 + ks * 16 + 8 * ((lane >> 3) & 1);
                ldsm4(bh, sb + SM_W2 + nrow * 528 + kcol * 2);
                #pragma unroll
                for (int tm = 0; tm < 2; ++tm) {
                    mma_f16(acc[tm][2*tp    ], af[tm][ks], &bh[0]);
                    mma_f16(acc[tm][2*tp + 1], af[tm][ks], &bh[2]);
                }
            }
        }
    }
    __syncthreads();   // all W2 reads done CTA-wide; W2 region reusable

    // stage W3^T into W2's region via cp.async (overlaps epilogue below)
    {
        const char* srcH = (const char*)g_W3TB;
        #pragma unroll
        for (int i = 0; i < 5; ++i) {
            const int t = tid + 256 * i;
            if (t < 1088) cp_async16(sb + SM_W3 + t * 16, srcH + t * 16);
        }
        CP_ASYNC_COMMIT();
    }
    // layer2 epilogue: bias+relu -> fp16 -> h2[m][k]
    {
        uint32_t* hh = reinterpret_cast<uint32_t*>(smem + SM_H2);
        #pragma unroll
        for (int tm = 0; tm < 2; ++tm) {
            #pragma unroll
            for (int tn = 0; tn < 8; ++tn) {
                const int n = wn * 64 + tn * 8 + (lane & 3) * 2;
                const int m = wm * 32 + tm * 16 + (lane >> 2);
                const float bn0 = b2s[n], bn1 = b2s[n + 1];
                #pragma unroll
                for (int rr = 0; rr < 2; ++rr) {
                    const float x0 = frelu(acc[tm][tn][2*rr    ] + bn0);
                    const float x1 = frelu(acc[tm][tn][2*rr + 1] + bn1);
                    hh[(m + 8*rr) * 68 + (n >> 1)] =
                        pack2h(__float2half_rn(x0), __float2half_rn(x1));
                }
            }
        }
    }
    CP_ASYNC_WAIT0();
    __syncthreads();

    // =================== layer3: h2[128x128] @ W3[128x64] ===================
    float acc3[2][4][4];
    #pragma unroll
    for (int a = 0; a < 2; a++)
        #pragma unroll
        for (int b = 0; b < 4; b++)
            #pragma unroll
            for (int c = 0; c < 4; c++) acc3[a][b][c] = 0.0f;

    #pragma unroll
    for (int ks = 0; ks < 8; ++ks) {
        uint32_t afr[2][4];
        #pragma unroll
        for (int tm = 0; tm < 2; ++tm) {
            const int mrow = wm * 32 + tm * 16 + (lane & 7) + 8 * ((lane >> 3) & 1);
            const int kcol = ks * 16 + 8 * (lane >> 4);
            ldsm4(afr[tm], sb + SM_H2 + mrow * 272 + kcol * 2);
        }
        #pragma unroll
        for (int tp = 0; tp < 2; ++tp) {
            uint32_t bh[4];
            const int nrow = wn * 32 + tp * 16 + (lane & 7) + 8 * (lane >> 4);
            const int kcol = ks * 16 + 8 * ((lane >> 3) & 1);
            ldsm4(bh, sb + SM_W3 + nrow * 272 + kcol * 2);
            #pragma unroll
            for (int tm = 0; tm < 2; ++tm) {
                mma_f16(acc3[tm][2*tp    ], afr[tm], &bh[0]);
                mma_f16(acc3[tm][2*tp + 1], afr[tm], &bh[2]);
            }
        }
    }

    // ============== layer3 epilogue + layer4 (registers + shfl) =============
    float part[4] = {0.0f, 0.0f, 0.0f, 0.0f};
    #pragma unroll
    for (int tn = 0; tn < 4; ++tn) {
        const int n = wn * 32 + tn * 8 + (lane & 3) * 2;
        const float bn0 = b3s[n], bn1 = b3s[n + 1];
        const float w0 = W4s[n],  w1 = W4s[n + 1];
        #pragma unroll
        for (int tm = 0; tm < 2; ++tm) {
            #pragma unroll
            for (int rr = 0; rr < 2; ++rr) {
                part[tm*2 + rr] += frelu(acc3[tm][tn][2*rr    ] + bn0) * w0
                                 + frelu(acc3[tm][tn][2*rr + 1] + bn1) * w1;
            }
        }
    }
    #pragma unroll
    for (int i = 0; i < 4; ++i) {
        part[i] += __shfl_xor_sync(0xffffffffu, part[i], 1);
        part[i] += __shfl_xor_sync(0xffffffffu, part[i], 2);
    }
    if ((lane & 3) == 0) {
        #pragma unroll
        for (int tm = 0; tm < 2; ++tm)
            #pragma unroll
            for (int rr = 0; rr < 2; ++rr) {
                const int m = wm * 32 + tm * 16 + rr * 8 + (lane >> 2);
                red[wn * 128 + m] = part[tm*2 + rr];
            }
    }
    __syncthreads();
    if (tid < 128) {
        const float v = red[tid] + red[128 + tid] + b4[0];
        out[(q0 + tid) * NS + s_idx] = 1.0f / (1.0f + expf(-v));
    }
}

// ---------------------------------------------------------------------------
extern "C" void kernel_launch(void* const* d_in, const int* in_sizes, int n_in,
                              void* d_out, int out_size)
{
    const float* qf = (const float*)d_in[0];
    const float* sf = (const float*)d_in[1];
    // d_in[2] = support_y (unused)
    const float* W1 = (const float*)d_in[3];
    const float* b1 = (const float*)d_in[4];
    const float* W2 = (const float*)d_in[5];
    const float* b2 = (const float*)d_in[6];
    const float* W3 = (const float*)d_in[7];
    const float* b3 = (const float*)d_in[8];
    const float* W4 = (const float*)d_in[9];
    const float* b4 = (const float*)d_in[10];
    float* out = (float*)d_out;

    cudaFuncSetAttribute(relation_mma_kernel,
                         cudaFuncAttributeMaxDynamicSharedMemorySize, SMEM_TOTAL);
    cudaFuncSetAttribute(precompute_mma_kernel,
                         cudaFuncAttributeMaxDynamicSharedMemorySize, PRE_SMEM_TOTAL);

    precompute_mma_kernel<<<dim3(45, 2), 512, PRE_SMEM_TOTAL>>>(qf, sf, b1, W1, W2, W3);
    relation_mma_kernel<<<dim3(NS, NQ / TM), 256, SMEM_TOTAL>>>(b2, b3, W4, b4, out);
}